// round 9
// baseline (speedup 1.0000x reference)
#include <cuda_runtime.h>
#include <cuda_bf16.h>
#include <math.h>
#include <stdint.h>

#define Bz 4
#define Tz 1024
#define Cz 768
#define Hz 12
#define HDz 64
#define Lz 6
#define Vz 32000
#define BT (Bz*Tz)

// ---------------- scratch (static device globals; no allocations) ----------
__device__ float g_x[BT*Cz];                     // residual stream (fp32)
__device__ __nv_bfloat16 g_lnh[BT*Cz], g_lnl[BT*Cz];     // layernorm out hi/lo
__device__ float g_qkv[BT*3*Cz];                 // qkv (fp32, attention input)
__device__ __nv_bfloat16 g_yh[BT*Cz], g_yl[BT*Cz];       // attention out hi/lo
__device__ __nv_bfloat16 g_hh[BT*4*Cz], g_hl[BT*4*Cz];   // MLP hidden hi/lo
// transposed bf16 hi/lo weights: Wt[N,K] row-major (K contiguous)
__device__ __nv_bfloat16 g_wqkv_h[Lz*3*Cz*Cz], g_wqkv_l[Lz*3*Cz*Cz];
__device__ __nv_bfloat16 g_wproj_h[Lz*Cz*Cz],  g_wproj_l[Lz*Cz*Cz];
__device__ __nv_bfloat16 g_wfc_h[Lz*4*Cz*Cz],  g_wfc_l[Lz*4*Cz*Cz];
__device__ __nv_bfloat16 g_wmlp_h[Lz*Cz*4*Cz], g_wmlp_l[Lz*Cz*4*Cz];
__device__ __nv_bfloat16 g_whead_h[Vz*Cz],     g_whead_l[Vz*Cz];

// ---------------- helpers ---------------------------------------------------
__device__ __forceinline__ uint32_t smem_u32(const void* p) {
    uint32_t a;
    asm("{ .reg .u64 t; cvta.to.shared.u64 t, %1; cvt.u32.u64 %0, t; }"
        : "=r"(a) : "l"(p));
    return a;
}
__device__ __forceinline__ void cpasync16(uint32_t s, const void* g) {
    asm volatile("cp.async.cg.shared.global [%0], [%1], 16;\n" :: "r"(s), "l"(g));
}
#define CP_COMMIT() asm volatile("cp.async.commit_group;\n" ::: "memory")

__device__ __forceinline__ void ldm_x4(uint32_t* r, uint32_t addr) {
    asm volatile("ldmatrix.sync.aligned.m8n8.x4.shared.b16 {%0,%1,%2,%3}, [%4];"
        : "=r"(r[0]), "=r"(r[1]), "=r"(r[2]), "=r"(r[3]) : "r"(addr));
}
__device__ __forceinline__ void mma16816(float* d, const uint32_t* a,
                                         uint32_t b0, uint32_t b1) {
    asm volatile("mma.sync.aligned.m16n8k16.row.col.f32.bf16.bf16.f32 "
        "{%0,%1,%2,%3}, {%4,%5,%6,%7}, {%8,%9}, {%0,%1,%2,%3};"
        : "+f"(d[0]), "+f"(d[1]), "+f"(d[2]), "+f"(d[3])
        : "r"(a[0]), "r"(a[1]), "r"(a[2]), "r"(a[3]), "r"(b0), "r"(b1));
}

__device__ __forceinline__ void split_bf16(float v, __nv_bfloat16& hi, __nv_bfloat16& lo) {
    hi = __float2bfloat16(v);
    lo = __float2bfloat16(v - __bfloat162float(hi));
}
__device__ __forceinline__ float gelu_exact(float v) {
    return 0.5f * v * (1.0f + erff(v * 0.70710678118654752f));
}

// ---------------- embedding ------------------------------------------------
__global__ void k_embed(const int* __restrict__ idx,
                        const float* __restrict__ wte,
                        const float* __restrict__ wpe) {
    int i = blockIdx.x * blockDim.x + threadIdx.x;
    if (i >= BT*Cz) return;
    int c  = i % Cz;
    int bt = i / Cz;
    int t  = bt % Tz;
    int tok = idx[bt];
    g_x[i] = wte[(size_t)tok * Cz + c] + wpe[(size_t)t * Cz + c];
}

// ---------------- weight transpose + bf16 hi/lo split ----------------------
__global__ void k_wprep(const float* __restrict__ W,
                        __nv_bfloat16* __restrict__ Whi,
                        __nv_bfloat16* __restrict__ Wlo, int K, int N) {
    __shared__ float t[32][33];
    int n0 = blockIdx.x * 32, k0 = blockIdx.y * 32;
    int tx = threadIdx.x, ty = threadIdx.y;   // 32 x 8
    #pragma unroll
    for (int j = 0; j < 32; j += 8)
        t[ty + j][tx] = W[(size_t)(k0 + ty + j) * N + n0 + tx];
    __syncthreads();
    #pragma unroll
    for (int j = 0; j < 32; j += 8) {
        float v = t[tx][ty + j];
        __nv_bfloat16 hi, lo; split_bf16(v, hi, lo);
        size_t o = (size_t)(n0 + ty + j) * K + k0 + tx;
        Whi[o] = hi; Wlo[o] = lo;
    }
}

// ---------------- layernorm -> bf16 hi/lo ----------------------------------
__global__ void k_ln(const float* __restrict__ x,
                     const float* __restrict__ w,
                     const float* __restrict__ b,
                     __nv_bfloat16* __restrict__ ohi,
                     __nv_bfloat16* __restrict__ olo) {
    int row = blockIdx.x;
    int tid = threadIdx.x;
    const float* xr = x + (size_t)row * Cz;
    float v0 = xr[tid], v1 = xr[tid + 256], v2 = xr[tid + 512];

    __shared__ float red[256];
    red[tid] = v0 + v1 + v2;
    __syncthreads();
    #pragma unroll
    for (int off = 128; off > 0; off >>= 1) {
        if (tid < off) red[tid] += red[tid + off];
        __syncthreads();
    }
    float mean = red[0] * (1.0f / Cz);
    __syncthreads();
    float d0 = v0 - mean, d1 = v1 - mean, d2 = v2 - mean;
    red[tid] = d0*d0 + d1*d1 + d2*d2;
    __syncthreads();
    #pragma unroll
    for (int off = 128; off > 0; off >>= 1) {
        if (tid < off) red[tid] += red[tid + off];
        __syncthreads();
    }
    float rstd = rsqrtf(red[0] * (1.0f / Cz) + 1e-5f);

    size_t base = (size_t)row * Cz;
    float r0 = d0 * rstd * w[tid]       + b[tid];
    float r1 = d1 * rstd * w[tid + 256] + b[tid + 256];
    float r2 = d2 * rstd * w[tid + 512] + b[tid + 512];
    __nv_bfloat16 hi, lo;
    split_bf16(r0, hi, lo); ohi[base + tid]       = hi; olo[base + tid]       = lo;
    split_bf16(r1, hi, lo); ohi[base + tid + 256] = hi; olo[base + tid + 256] = lo;
    split_bf16(r2, hi, lo); ohi[base + tid + 512] = hi; olo[base + tid + 512] = lo;
}

// ---------------- mma.sync GEMM: BM=64, BN=128, K32 x 3-stage, 2 CTAs/SM ---
// out[M,N] = (Ahi+Alo)[M,K] @ (Bhi+Blo)[N,K]^T   (3-product bf16 split)
// mode: 0 = +bias->fp32 | 1 = +bias+res->fp32 | 2 = gelu(+bias)->bf16 hi/lo
//       3 = plain->fp32.   8 warps as 2(M)x4(N); warp tile 32x32.
// Single __syncthreads per chunk: with 3 stages, the load for chunk i+2
// targets the stage consumed at iteration i-1, finished by all warps at the
// top-of-loop barrier of iteration i.
#define MMR 80                         // row stride bytes (64 data + 16 pad)
#define MG_ABYTES (64*MMR)             // 5120
#define MG_BBYTES (128*MMR)            // 10240
#define MG_STAGE (2*MG_ABYTES + 2*MG_BBYTES)   // 30720
#define MG_SMEM (3*MG_STAGE)                   // 92160 -> 2 CTAs/SM

__global__ void __launch_bounds__(256, 2) k_mgemm(
    const __nv_bfloat16* __restrict__ Ahi, const __nv_bfloat16* __restrict__ Alo,
    const __nv_bfloat16* __restrict__ Bhi, const __nv_bfloat16* __restrict__ Blo,
    const float* __restrict__ bias, const float* res,
    float* outf, __nv_bfloat16* outhi, __nv_bfloat16* outlo,
    int M, int N, int K, int mode) {
    extern __shared__ char smem[];
    uint32_t sbase = smem_u32(smem);
    int tid = threadIdx.x, lane = tid & 31, warp = tid >> 5;
    int wm = (warp >> 2) * 32;           // warp M offset (0/32)
    int wn = (warp & 3) * 32;            // warp N offset (0..96)
    int gn0 = blockIdx.x * 128, gm0 = blockIdx.y * 64;
    int nch = K >> 5;                    // K32 chunks

    // ---- precomputed load slots: r0 = tid>>2 (0..63), seg = tid&3 ----
    int r0 = tid >> 2, seg = tid & 3;
    const __nv_bfloat16* sAh = Ahi + (size_t)(gm0 + r0) * K + seg * 8;
    const __nv_bfloat16* sAl = Alo + (size_t)(gm0 + r0) * K + seg * 8;
    const __nv_bfloat16* sBh = Bhi + (size_t)(gn0 + r0) * K + seg * 8;
    const __nv_bfloat16* sBl = Blo + (size_t)(gn0 + r0) * K + seg * 8;
    const __nv_bfloat16* sBh2 = sBh + (size_t)64 * K;
    const __nv_bfloat16* sBl2 = sBl + (size_t)64 * K;
    uint32_t dsto = (uint32_t)(r0 * MMR + seg * 16);

    auto load_chunk = [&](int stage, int chunk) {
        uint32_t so = sbase + stage * MG_STAGE + dsto;
        size_t ko = (size_t)chunk * 32;
        cpasync16(so,                          sAh + ko);
        cpasync16(so + MG_ABYTES,              sAl + ko);
        cpasync16(so + 2*MG_ABYTES,            sBh + ko);
        cpasync16(so + 2*MG_ABYTES + 5120,     sBh2 + ko);
        cpasync16(so + 2*MG_ABYTES + MG_BBYTES,        sBl + ko);
        cpasync16(so + 2*MG_ABYTES + MG_BBYTES + 5120, sBl2 + ko);
        CP_COMMIT();
    };

    float acc[2][4][4];
    #pragma unroll
    for (int i = 0; i < 2; i++)
        #pragma unroll
        for (int j = 0; j < 4; j++)
            #pragma unroll
            for (int e = 0; e < 4; e++) acc[i][j][e] = 0.f;

    load_chunk(0, 0);
    load_chunk(1, 1);

    int lrow = lane & 15;
    int lkb  = (lane >> 4) * 16;         // k-half byte offset

    for (int i = 0; i < nch; i++) {
        if (i + 1 < nch) asm volatile("cp.async.wait_group 1;\n" ::: "memory");
        else             asm volatile("cp.async.wait_group 0;\n" ::: "memory");
        __syncthreads();

        uint32_t so = sbase + (i % 3) * MG_STAGE;
        uint32_t arow = so + (wm + lrow) * MMR;
        uint32_t brow = so + 2 * MG_ABYTES + (wn + lrow) * MMR;

        #pragma unroll
        for (int ks = 0; ks < 2; ks++) {
            uint32_t kb = (uint32_t)(ks * 32) + lkb;
            uint32_t ah[2][4], al[2][4], bh[2][4], bl[2][4];
            #pragma unroll
            for (int mt = 0; mt < 2; mt++) {
                ldm_x4(ah[mt], arow + mt * (16 * MMR) + kb);
                ldm_x4(al[mt], arow + MG_ABYTES + mt * (16 * MMR) + kb);
            }
            #pragma unroll
            for (int np = 0; np < 2; np++) {
                ldm_x4(bh[np], brow + np * (16 * MMR) + kb);
                ldm_x4(bl[np], brow + MG_BBYTES + np * (16 * MMR) + kb);
            }
            // product-major: 8 independent MMAs between same-acc touches
            #pragma unroll
            for (int mt = 0; mt < 2; mt++)
                #pragma unroll
                for (int nt = 0; nt < 4; nt++) {
                    int np = nt >> 1, h = nt & 1;
                    mma16816(acc[mt][nt], ah[mt], bh[np][h], bh[np][h + 2]);
                }
            #pragma unroll
            for (int mt = 0; mt < 2; mt++)
                #pragma unroll
                for (int nt = 0; nt < 4; nt++) {
                    int np = nt >> 1, h = nt & 1;
                    mma16816(acc[mt][nt], al[mt], bh[np][h], bh[np][h + 2]);
                }
            #pragma unroll
            for (int mt = 0; mt < 2; mt++)
                #pragma unroll
                for (int nt = 0; nt < 4; nt++) {
                    int np = nt >> 1, h = nt & 1;
                    mma16816(acc[mt][nt], ah[mt], bl[np][h], bl[np][h + 2]);
                }
        }
        // no second barrier: 3-stage rotation makes the target stage safe
        if (i + 2 < nch) load_chunk((i + 2) % 3, i + 2);
    }

    // epilogue
    int r  = lane >> 2;
    int c2 = (lane & 3) * 2;
    #pragma unroll
    for (int mt = 0; mt < 2; mt++) {
        #pragma unroll
        for (int nt = 0; nt < 4; nt++) {
            int m = gm0 + wm + mt * 16 + r;
            int n = gn0 + wn + nt * 8 + c2;
            float* d = acc[mt][nt];
            #pragma unroll
            for (int hh = 0; hh < 2; hh++) {
                int mm = m + hh * 8;
                float v0 = d[2*hh], v1 = d[2*hh + 1];
                if (mode == 2) {
                    v0 = gelu_exact(v0 + bias[n]);
                    v1 = gelu_exact(v1 + bias[n + 1]);
                    __nv_bfloat16 h0, l0, h1, l1;
                    split_bf16(v0, h0, l0); split_bf16(v1, h1, l1);
                    *(__nv_bfloat162*)(outhi + (size_t)mm * N + n) = __nv_bfloat162(h0, h1);
                    *(__nv_bfloat162*)(outlo + (size_t)mm * N + n) = __nv_bfloat162(l0, l1);
                } else {
                    if (mode != 3) { v0 += bias[n]; v1 += bias[n + 1]; }
                    if (mode == 1) {
                        const float2 rv = *(const float2*)(res + (size_t)mm * N + n);
                        v0 += rv.x; v1 += rv.y;
                    }
                    *(float2*)(outf + (size_t)mm * N + n) = make_float2(v0, v1);
                }
            }
        }
    }
}

// ---------------- flash-tiled causal attention -----------------------------
#define ASTR 68                         // floats per smem row (272B, 16B-mult)
#define ASMEM (4 * 64 * ASTR * 4)       // Qs, Ks, Vs, Ps

__global__ void __launch_bounds__(256) k_fattn(
    const float* __restrict__ qkv,
    __nv_bfloat16* __restrict__ yh, __nv_bfloat16* __restrict__ yl) {
    extern __shared__ float sm[];
    float* Qs = sm;
    float* Ks = sm + 64 * ASTR;
    float* Vs = sm + 2 * 64 * ASTR;
    float* Ps = sm + 3 * 64 * ASTR;

    int q0 = blockIdx.x * 64, h = blockIdx.y, b = blockIdx.z;
    int tid = threadIdx.x, lane = tid & 31, warp = tid >> 5;
    int r = lane >> 2, c = lane & 3;
    int qrow = warp * 8 + r;             // local query row
    int qglob = q0 + qrow;

    {
        const float4* g = (const float4*)qkv;
        float4* s4 = (float4*)Qs;
        for (int i = tid; i < 1024; i += 256) {
            int row = i >> 4, sg = i & 15;
            s4[row * 17 + sg] = g[((size_t)(b * Tz + q0 + row) * (3*Cz) + h * 64) / 4 + sg];
        }
    }

    float mrow = -1e30f, lrow = 0.f;
    float oacc[16];
    #pragma unroll
    for (int i = 0; i < 16; i++) oacc[i] = 0.f;

    int ntiles = (q0 >> 6) + 1;
    for (int t = 0; t < ntiles; t++) {
        __syncthreads();
        {
            const float4* g = (const float4*)qkv;
            float4* k4 = (float4*)Ks;
            float4* v4 = (float4*)Vs;
            for (int i = tid; i < 1024; i += 256) {
                int row = i >> 4, sg = i & 15;
                size_t gb = ((size_t)(b * Tz + t * 64 + row) * (3*Cz) + h * 64) / 4 + sg;
                k4[row * 17 + sg] = g[gb + Cz / 4];
                v4[row * 17 + sg] = g[gb + 2 * Cz / 4];
            }
        }
        __syncthreads();

        float s[16];
        #pragma unroll
        for (int kk = 0; kk < 16; kk++) s[kk] = 0.f;
        const float4* q4 = (const float4*)Qs + qrow * 17;
        const float4* k4b = (const float4*)Ks;
        #pragma unroll 4
        for (int d4 = 0; d4 < 16; d4++) {
            float4 qv = q4[d4];
            #pragma unroll
            for (int kk = 0; kk < 16; kk++) {
                float4 kv = k4b[(kk * 4 + c) * 17 + d4];
                s[kk] += qv.x * kv.x + qv.y * kv.y + qv.z * kv.z + qv.w * kv.w;
            }
        }
        bool maskt = (t == ntiles - 1);
        float tmax = -1e30f;
        #pragma unroll
        for (int kk = 0; kk < 16; kk++) {
            s[kk] *= 0.125f;
            if (maskt && (t * 64 + kk * 4 + c) > qglob) s[kk] = -1e30f;
            tmax = fmaxf(tmax, s[kk]);
        }
        tmax = fmaxf(tmax, __shfl_xor_sync(0xffffffffu, tmax, 1));
        tmax = fmaxf(tmax, __shfl_xor_sync(0xffffffffu, tmax, 2));
        float mnew = fmaxf(mrow, tmax);
        float scale = __expf(mrow - mnew);
        float psum = 0.f;
        #pragma unroll
        for (int kk = 0; kk < 16; kk++) {
            float p = __expf(s[kk] - mnew);
            s[kk] = p;
            psum += p;
            Ps[qrow * ASTR + kk * 4 + c] = p;
        }
        psum += __shfl_xor_sync(0xffffffffu, psum, 1);
        psum += __shfl_xor_sync(0xffffffffu, psum, 2);
        lrow = lrow * scale + psum;
        #pragma unroll
        for (int i = 0; i < 16; i++) oacc[i] *= scale;
        mrow = mnew;
        __syncwarp();

        const float4* p4 = (const float4*)Ps + qrow * 17;
        const float4* v4b = (const float4*)Vs;
        #pragma unroll 2
        for (int kq = 0; kq < 16; kq++) {
            float4 pv = p4[kq];
            #pragma unroll
            for (int j = 0; j < 4; j++) {
                float pj = (j == 0) ? pv.x : (j == 1) ? pv.y : (j == 2) ? pv.z : pv.w;
                const float4* vr = v4b + (kq * 4 + j) * 17 + c * 4;
                #pragma unroll
                for (int e = 0; e < 4; e++) {
                    float4 vv = vr[e];
                    oacc[e*4+0] += pj * vv.x;
                    oacc[e*4+1] += pj * vv.y;
                    oacc[e*4+2] += pj * vv.z;
                    oacc[e*4+3] += pj * vv.w;
                }
            }
        }
    }

    float inv = 1.0f / lrow;
    size_t base = (size_t)(b * Tz + qglob) * Cz + h * 64 + c * 16;
    #pragma unroll
    for (int g = 0; g < 8; g++) {
        float v0 = oacc[2*g] * inv, v1 = oacc[2*g+1] * inv;
        __nv_bfloat16 h0, l0, h1, l1;
        split_bf16(v0, h0, l0); split_bf16(v1, h1, l1);
        *(__nv_bfloat162*)(yh + base + 2*g) = __nv_bfloat162(h0, h1);
        *(__nv_bfloat162*)(yl + base + 2*g) = __nv_bfloat162(l0, l1);
    }
}

// ---------------- driver ----------------------------------------------------
extern "C" void kernel_launch(void* const* d_in, const int* in_sizes, int n_in,
                              void* d_out, int out_size) {
    const int*   idx    = (const int*)  d_in[0];
    const float* wte    = (const float*)d_in[1];
    const float* wpe    = (const float*)d_in[2];
    const float* ln1_w  = (const float*)d_in[3];
    const float* ln1_b  = (const float*)d_in[4];
    const float* attn_w = (const float*)d_in[5];
    const float* attn_b = (const float*)d_in[6];
    const float* proj_w = (const float*)d_in[7];
    const float* proj_b = (const float*)d_in[8];
    const float* ln2_w  = (const float*)d_in[9];
    const float* ln2_b  = (const float*)d_in[10];
    const float* fc_w   = (const float*)d_in[11];
    const float* fc_b   = (const float*)d_in[12];
    const float* mlp_w  = (const float*)d_in[13];
    const float* mlp_b  = (const float*)d_in[14];
    const float* lnf_w  = (const float*)d_in[15];
    const float* lnf_b  = (const float*)d_in[16];
    const float* head_w = (const float*)d_in[17];
    float* out = (float*)d_out;

    float *px, *pqkv;
    __nv_bfloat16 *plnh, *plnl, *pyh, *pyl, *phh, *phl;
    __nv_bfloat16 *wqh, *wql, *wph, *wpl, *wfh, *wfl, *wmh, *wml, *whh, *whl;
    cudaGetSymbolAddress((void**)&px,   g_x);
    cudaGetSymbolAddress((void**)&pqkv, g_qkv);
    cudaGetSymbolAddress((void**)&plnh, g_lnh);
    cudaGetSymbolAddress((void**)&plnl, g_lnl);
    cudaGetSymbolAddress((void**)&pyh,  g_yh);
    cudaGetSymbolAddress((void**)&pyl,  g_yl);
    cudaGetSymbolAddress((void**)&phh,  g_hh);
    cudaGetSymbolAddress((void**)&phl,  g_hl);
    cudaGetSymbolAddress((void**)&wqh,  g_wqkv_h);
    cudaGetSymbolAddress((void**)&wql,  g_wqkv_l);
    cudaGetSymbolAddress((void**)&wph,  g_wproj_h);
    cudaGetSymbolAddress((void**)&wpl,  g_wproj_l);
    cudaGetSymbolAddress((void**)&wfh,  g_wfc_h);
    cudaGetSymbolAddress((void**)&wfl,  g_wfc_l);
    cudaGetSymbolAddress((void**)&wmh,  g_wmlp_h);
    cudaGetSymbolAddress((void**)&wml,  g_wmlp_l);
    cudaGetSymbolAddress((void**)&whh,  g_whead_h);
    cudaGetSymbolAddress((void**)&whl,  g_whead_l);

    cudaFuncSetAttribute(k_mgemm, cudaFuncAttributeMaxDynamicSharedMemorySize, MG_SMEM);
    cudaFuncSetAttribute(k_fattn, cudaFuncAttributeMaxDynamicSharedMemorySize, ASMEM);

    dim3 tp(32, 8);
    // ---- my launches 1-3, so that my launch #4 (= ncu capture slot) is
    // the QKV GEMM of layer 0 ----
    k_wprep<<<dim3(3*Cz/32, Cz/32), tp>>>(attn_w, wqh, wql, Cz, 3*Cz);   // 1
    k_embed<<<(BT*Cz + 255) / 256, 256>>>(idx, wte, wpe);                // 2
    k_ln<<<BT, 256>>>(px, ln1_w, ln1_b, plnh, plnl);                     // 3
    // 4: QKV GEMM of layer 0 (ncu capture target)
    k_mgemm<<<dim3(3*Cz/128, BT/64), 256, MG_SMEM>>>(
        plnh, plnl, wqh, wql, attn_b, nullptr, pqkv, nullptr, nullptr,
        BT, 3*Cz, Cz, 0);

    // remaining weight preps
    k_wprep<<<dim3(Cz/32, Cz/32), tp>>>(proj_w, wph, wpl, Cz, Cz);
    k_wprep<<<dim3(4*Cz/32, Cz/32), tp>>>(fc_w, wfh, wfl, Cz, 4*Cz);
    k_wprep<<<dim3(Cz/32, 4*Cz/32), tp>>>(mlp_w, wmh, wml, 4*Cz, Cz);
    for (int l = 1; l < Lz; l++) {
        k_wprep<<<dim3(3*Cz/32, Cz/32), tp>>>(attn_w + (size_t)l*Cz*3*Cz,
            wqh + (size_t)l*3*Cz*Cz, wql + (size_t)l*3*Cz*Cz, Cz, 3*Cz);
        k_wprep<<<dim3(Cz/32, Cz/32), tp>>>(proj_w + (size_t)l*Cz*Cz,
            wph + (size_t)l*Cz*Cz, wpl + (size_t)l*Cz*Cz, Cz, Cz);
        k_wprep<<<dim3(4*Cz/32, Cz/32), tp>>>(fc_w + (size_t)l*Cz*4*Cz,
            wfh + (size_t)l*4*Cz*Cz, wfl + (size_t)l*4*Cz*Cz, Cz, 4*Cz);
        k_wprep<<<dim3(Cz/32, 4*Cz/32), tp>>>(mlp_w + (size_t)l*4*Cz*Cz,
            wmh + (size_t)l*Cz*4*Cz, wml + (size_t)l*Cz*4*Cz, 4*Cz, Cz);
    }
    k_wprep<<<dim3(Vz/32, Cz/32), tp>>>(head_w, whh, whl, Cz, Vz);

    for (int l = 0; l < Lz; l++) {
        const float* ab = attn_b + (size_t)l * 3 * Cz;
        const float* pb = proj_b + (size_t)l * Cz;
        const float* fb = fc_b   + (size_t)l * 4 * Cz;
        const float* mb = mlp_b  + (size_t)l * Cz;

        if (l > 0) {
            k_ln<<<BT, 256>>>(px, ln1_w + (size_t)l*Cz, ln1_b + (size_t)l*Cz, plnh, plnl);
            k_mgemm<<<dim3(3*Cz/128, BT/64), 256, MG_SMEM>>>(
                plnh, plnl, wqh + (size_t)l*3*Cz*Cz, wql + (size_t)l*3*Cz*Cz,
                ab, nullptr, pqkv, nullptr, nullptr, BT, 3*Cz, Cz, 0);
        }
        k_fattn<<<dim3(Tz/64, Hz, Bz), 256, ASMEM>>>(pqkv, pyh, pyl);
        // x += y @ Wproj + b       [4096, 768]
        k_mgemm<<<dim3(Cz/128, BT/64), 256, MG_SMEM>>>(
            pyh, pyl, wph + (size_t)l*Cz*Cz, wpl + (size_t)l*Cz*Cz,
            pb, px, px, nullptr, nullptr, BT, Cz, Cz, 1);
        k_ln<<<BT, 256>>>(px, ln2_w + (size_t)l*Cz, ln2_b + (size_t)l*Cz, plnh, plnl);
        // h = gelu(ln2 @ Wfc + b)  [4096, 3072]
        k_mgemm<<<dim3(4*Cz/128, BT/64), 256, MG_SMEM>>>(
            plnh, plnl, wfh + (size_t)l*4*Cz*Cz, wfl + (size_t)l*4*Cz*Cz,
            fb, nullptr, nullptr, phh, phl, BT, 4*Cz, Cz, 2);
        // x += h @ Wmlp + b        [4096, 768], K=3072
        k_mgemm<<<dim3(Cz/128, BT/64), 256, MG_SMEM>>>(
            phh, phl, wmh + (size_t)l*Cz*4*Cz, wml + (size_t)l*Cz*4*Cz,
            mb, px, px, nullptr, nullptr, BT, Cz, 4*Cz, 1);
    }

    k_ln<<<BT, 256>>>(px, lnf_w, lnf_b, plnh, plnl);
    // logits = lnf @ Whead        [4096, 32000]
    k_mgemm<<<dim3(Vz/128, BT/64), 256, MG_SMEM>>>(
        plnh, plnl, whh, whl, nullptr, nullptr, out, nullptr, nullptr,
        BT, Vz, Cz, 3);
}

// round 10
// speedup vs baseline: 1.0877x; 1.0877x over previous
#include <cuda_runtime.h>
#include <cuda_bf16.h>
#include <math.h>
#include <stdint.h>

#define Bz 4
#define Tz 1024
#define Cz 768
#define Hz 12
#define HDz 64
#define Lz 6
#define Vz 32000
#define BT (Bz*Tz)

// ---------------- scratch (static device globals; no allocations) ----------
__device__ float g_x[BT*Cz];                     // residual stream (fp32)
__device__ __nv_bfloat16 g_lnh[BT*Cz], g_lnl[BT*Cz];     // layernorm out hi/lo
__device__ float g_qkv[BT*3*Cz];                 // qkv (fp32, attention input)
__device__ __nv_bfloat16 g_yh[BT*Cz], g_yl[BT*Cz];       // attention out hi/lo
__device__ __nv_bfloat16 g_hh[BT*4*Cz], g_hl[BT*4*Cz];   // MLP hidden hi/lo
// transposed bf16 hi/lo weights: Wt[N,K] row-major (K contiguous)
__device__ __nv_bfloat16 g_wqkv_h[Lz*3*Cz*Cz], g_wqkv_l[Lz*3*Cz*Cz];
__device__ __nv_bfloat16 g_wproj_h[Lz*Cz*Cz],  g_wproj_l[Lz*Cz*Cz];
__device__ __nv_bfloat16 g_wfc_h[Lz*4*Cz*Cz],  g_wfc_l[Lz*4*Cz*Cz];
__device__ __nv_bfloat16 g_wmlp_h[Lz*Cz*4*Cz], g_wmlp_l[Lz*Cz*4*Cz];
// tf32 head path: fragment-ready permuted layouts
__device__ float g_whead_t[(size_t)Vz*Cz];       // B-perm tf32
__device__ float g_lnt[BT*Cz];                   // A-perm tf32 (final LN out)

// ---------------- helpers ---------------------------------------------------
__device__ __forceinline__ uint32_t smem_u32(const void* p) {
    uint32_t a;
    asm("{ .reg .u64 t; cvta.to.shared.u64 t, %1; cvt.u32.u64 %0, t; }"
        : "=r"(a) : "l"(p));
    return a;
}
__device__ __forceinline__ void cpasync16(uint32_t s, const void* g) {
    asm volatile("cp.async.cg.shared.global [%0], [%1], 16;\n" :: "r"(s), "l"(g));
}
#define CP_COMMIT() asm volatile("cp.async.commit_group;\n" ::: "memory")

__device__ __forceinline__ void ldm_x4(uint32_t* r, uint32_t addr) {
    asm volatile("ldmatrix.sync.aligned.m8n8.x4.shared.b16 {%0,%1,%2,%3}, [%4];"
        : "=r"(r[0]), "=r"(r[1]), "=r"(r[2]), "=r"(r[3]) : "r"(addr));
}
__device__ __forceinline__ void lds128(uint32_t* r, uint32_t addr) {
    asm volatile("ld.shared.v4.b32 {%0,%1,%2,%3}, [%4];"
        : "=r"(r[0]), "=r"(r[1]), "=r"(r[2]), "=r"(r[3]) : "r"(addr));
}
__device__ __forceinline__ void mma16816(float* d, const uint32_t* a,
                                         uint32_t b0, uint32_t b1) {
    asm volatile("mma.sync.aligned.m16n8k16.row.col.f32.bf16.bf16.f32 "
        "{%0,%1,%2,%3}, {%4,%5,%6,%7}, {%8,%9}, {%0,%1,%2,%3};"
        : "+f"(d[0]), "+f"(d[1]), "+f"(d[2]), "+f"(d[3])
        : "r"(a[0]), "r"(a[1]), "r"(a[2]), "r"(a[3]), "r"(b0), "r"(b1));
}
__device__ __forceinline__ void mma_tf32(float* d, const uint32_t* a,
                                         uint32_t b0, uint32_t b1) {
    asm volatile("mma.sync.aligned.m16n8k8.row.col.f32.tf32.tf32.f32 "
        "{%0,%1,%2,%3}, {%4,%5,%6,%7}, {%8,%9}, {%0,%1,%2,%3};"
        : "+f"(d[0]), "+f"(d[1]), "+f"(d[2]), "+f"(d[3])
        : "r"(a[0]), "r"(a[1]), "r"(a[2]), "r"(a[3]), "r"(b0), "r"(b1));
}
__device__ __forceinline__ float tf32r(float x) {
    uint32_t r;
    asm("cvt.rna.tf32.f32 %0, %1;" : "=r"(r) : "f"(x));
    return __uint_as_float(r);
}
__device__ __forceinline__ void split_bf16(float v, __nv_bfloat16& hi, __nv_bfloat16& lo) {
    hi = __float2bfloat16(v);
    lo = __float2bfloat16(v - __bfloat162float(hi));
}
__device__ __forceinline__ float gelu_exact(float v) {
    return 0.5f * v * (1.0f + erff(v * 0.70710678118654752f));
}

// permuted-layout index helpers (tf32 fragment-ready)
// A-perm: element (m,k): tile (m/16, k/8), lane = (m&7)*4+(k&3),
//         slot = ((m>>3)&1) + 2*((k>>2)&1)
__device__ __forceinline__ size_t aperm_off(int m, int k, int K8) {
    return ((size_t)(m >> 4) * K8 + (k >> 3)) * 128
         + ((m & 7) * 4 + (k & 3)) * 4 + ((m >> 3) & 1) + 2 * ((k >> 2) & 1);
}
// B-perm: element (n,k): tile (n/16, k/8), lane = (n&7)*4+(k&3),
//         slot = ((k>>2)&1) + 2*((n>>3)&1)
__device__ __forceinline__ size_t bperm_off(int n, int k, int K8) {
    return ((size_t)(n >> 4) * K8 + (k >> 3)) * 128
         + ((n & 7) * 4 + (k & 3)) * 4 + ((k >> 2) & 1) + 2 * ((n >> 3) & 1);
}

// ---------------- fused embed + layer-0 ln1 --------------------------------
__global__ void k_embed_ln(const int* __restrict__ idx,
                           const float* __restrict__ wte,
                           const float* __restrict__ wpe,
                           const float* __restrict__ w,
                           const float* __restrict__ b,
                           __nv_bfloat16* __restrict__ ohi,
                           __nv_bfloat16* __restrict__ olo) {
    int row = blockIdx.x;
    int tid = threadIdx.x;
    int t = row % Tz;
    int tok = idx[row];
    const float* we = wte + (size_t)tok * Cz;
    const float* pe = wpe + (size_t)t * Cz;
    float v0 = we[tid] + pe[tid];
    float v1 = we[tid + 256] + pe[tid + 256];
    float v2 = we[tid + 512] + pe[tid + 512];
    size_t base = (size_t)row * Cz;
    g_x[base + tid] = v0; g_x[base + tid + 256] = v1; g_x[base + tid + 512] = v2;

    __shared__ float red[256];
    red[tid] = v0 + v1 + v2;
    __syncthreads();
    #pragma unroll
    for (int off = 128; off > 0; off >>= 1) {
        if (tid < off) red[tid] += red[tid + off];
        __syncthreads();
    }
    float mean = red[0] * (1.0f / Cz);
    __syncthreads();
    float d0 = v0 - mean, d1 = v1 - mean, d2 = v2 - mean;
    red[tid] = d0*d0 + d1*d1 + d2*d2;
    __syncthreads();
    #pragma unroll
    for (int off = 128; off > 0; off >>= 1) {
        if (tid < off) red[tid] += red[tid + off];
        __syncthreads();
    }
    float rstd = rsqrtf(red[0] * (1.0f / Cz) + 1e-5f);
    float r0 = d0 * rstd * w[tid]       + b[tid];
    float r1 = d1 * rstd * w[tid + 256] + b[tid + 256];
    float r2 = d2 * rstd * w[tid + 512] + b[tid + 512];
    __nv_bfloat16 hi, lo;
    split_bf16(r0, hi, lo); ohi[base + tid]       = hi; olo[base + tid]       = lo;
    split_bf16(r1, hi, lo); ohi[base + tid + 256] = hi; olo[base + tid + 256] = lo;
    split_bf16(r2, hi, lo); ohi[base + tid + 512] = hi; olo[base + tid + 512] = lo;
}

// ---------------- weight transpose + bf16 hi/lo split ----------------------
__global__ void k_wprep(const float* __restrict__ W,
                        __nv_bfloat16* __restrict__ Whi,
                        __nv_bfloat16* __restrict__ Wlo, int K, int N) {
    __shared__ float t[32][33];
    int n0 = blockIdx.x * 32, k0 = blockIdx.y * 32;
    int tx = threadIdx.x, ty = threadIdx.y;   // 32 x 8
    #pragma unroll
    for (int j = 0; j < 32; j += 8)
        t[ty + j][tx] = W[(size_t)(k0 + ty + j) * N + n0 + tx];
    __syncthreads();
    #pragma unroll
    for (int j = 0; j < 32; j += 8) {
        float v = t[tx][ty + j];
        __nv_bfloat16 hi, lo; split_bf16(v, hi, lo);
        size_t o = (size_t)(n0 + ty + j) * K + k0 + tx;
        Whi[o] = hi; Wlo[o] = lo;
    }
}

// ---------------- head weight -> B-perm tf32 -------------------------------
__global__ void k_wprep_head(const float* __restrict__ W,   // [Cz][Vz]
                             float* __restrict__ Wp) {
    __shared__ float t[32][33];
    int n0 = blockIdx.x * 32, k0 = blockIdx.y * 32;
    int tx = threadIdx.x, ty = threadIdx.y;   // 32 x 8
    #pragma unroll
    for (int j = 0; j < 32; j += 8)
        t[ty + j][tx] = W[(size_t)(k0 + ty + j) * Vz + n0 + tx];
    __syncthreads();
    #pragma unroll
    for (int j = 0; j < 32; j += 8) {
        int n = n0 + ty + j, k = k0 + tx;
        Wp[bperm_off(n, k, Cz >> 3)] = tf32r(t[tx][ty + j]);
    }
}

// ---------------- layernorm -> bf16 hi/lo ----------------------------------
__global__ void k_ln(const float* __restrict__ x,
                     const float* __restrict__ w,
                     const float* __restrict__ b,
                     __nv_bfloat16* __restrict__ ohi,
                     __nv_bfloat16* __restrict__ olo) {
    int row = blockIdx.x;
    int tid = threadIdx.x;
    const float* xr = x + (size_t)row * Cz;
    float v0 = xr[tid], v1 = xr[tid + 256], v2 = xr[tid + 512];

    __shared__ float red[256];
    red[tid] = v0 + v1 + v2;
    __syncthreads();
    #pragma unroll
    for (int off = 128; off > 0; off >>= 1) {
        if (tid < off) red[tid] += red[tid + off];
        __syncthreads();
    }
    float mean = red[0] * (1.0f / Cz);
    __syncthreads();
    float d0 = v0 - mean, d1 = v1 - mean, d2 = v2 - mean;
    red[tid] = d0*d0 + d1*d1 + d2*d2;
    __syncthreads();
    #pragma unroll
    for (int off = 128; off > 0; off >>= 1) {
        if (tid < off) red[tid] += red[tid + off];
        __syncthreads();
    }
    float rstd = rsqrtf(red[0] * (1.0f / Cz) + 1e-5f);

    size_t base = (size_t)row * Cz;
    float r0 = d0 * rstd * w[tid]       + b[tid];
    float r1 = d1 * rstd * w[tid + 256] + b[tid + 256];
    float r2 = d2 * rstd * w[tid + 512] + b[tid + 512];
    __nv_bfloat16 hi, lo;
    split_bf16(r0, hi, lo); ohi[base + tid]       = hi; olo[base + tid]       = lo;
    split_bf16(r1, hi, lo); ohi[base + tid + 256] = hi; olo[base + tid + 256] = lo;
    split_bf16(r2, hi, lo); ohi[base + tid + 512] = hi; olo[base + tid + 512] = lo;
}

// ---------------- final layernorm -> A-perm tf32 ---------------------------
__global__ void k_lnp(const float* __restrict__ x,
                      const float* __restrict__ w,
                      const float* __restrict__ b,
                      float* __restrict__ op) {
    int row = blockIdx.x;
    int tid = threadIdx.x;
    const float* xr = x + (size_t)row * Cz;
    float v0 = xr[tid], v1 = xr[tid + 256], v2 = xr[tid + 512];

    __shared__ float red[256];
    red[tid] = v0 + v1 + v2;
    __syncthreads();
    #pragma unroll
    for (int off = 128; off > 0; off >>= 1) {
        if (tid < off) red[tid] += red[tid + off];
        __syncthreads();
    }
    float mean = red[0] * (1.0f / Cz);
    __syncthreads();
    float d0 = v0 - mean, d1 = v1 - mean, d2 = v2 - mean;
    red[tid] = d0*d0 + d1*d1 + d2*d2;
    __syncthreads();
    #pragma unroll
    for (int off = 128; off > 0; off >>= 1) {
        if (tid < off) red[tid] += red[tid + off];
        __syncthreads();
    }
    float rstd = rsqrtf(red[0] * (1.0f / Cz) + 1e-5f);

    int K8 = Cz >> 3;
    op[aperm_off(row, tid,       K8)] = tf32r(d0 * rstd * w[tid]       + b[tid]);
    op[aperm_off(row, tid + 256, K8)] = tf32r(d1 * rstd * w[tid + 256] + b[tid + 256]);
    op[aperm_off(row, tid + 512, K8)] = tf32r(d2 * rstd * w[tid + 512] + b[tid + 512]);
}

// ---------------- bf16 mma.sync GEMM (R8-proven): BM=64, BN=128 ------------
#define MMR 144
#define MG_ABYTES (64*MMR)
#define MG_BBYTES (128*MMR)
#define MG_STAGE (2*MG_ABYTES + 2*MG_BBYTES)   // 55296
#define MG_SMEM (2*MG_STAGE)                   // 110592

__global__ void __launch_bounds__(256, 2) k_mgemm(
    const __nv_bfloat16* __restrict__ Ahi, const __nv_bfloat16* __restrict__ Alo,
    const __nv_bfloat16* __restrict__ Bhi, const __nv_bfloat16* __restrict__ Blo,
    const float* __restrict__ bias, const float* res,
    float* outf, __nv_bfloat16* outhi, __nv_bfloat16* outlo,
    int M, int N, int K, int mode) {
    extern __shared__ char smem[];
    uint32_t sbase = smem_u32(smem);
    int tid = threadIdx.x, lane = tid & 31, warp = tid >> 5;
    int wm = (warp >> 2) * 32;
    int wn = (warp & 3) * 32;
    int gn0 = blockIdx.x * 128, gm0 = blockIdx.y * 64;
    int nch = K >> 6;

    int r0 = tid >> 3, seg = tid & 7;
    const __nv_bfloat16* sAh = Ahi + (size_t)(gm0 + r0) * K + seg * 8;
    const __nv_bfloat16* sAl = Alo + (size_t)(gm0 + r0) * K + seg * 8;
    const __nv_bfloat16* sBh = Bhi + (size_t)(gn0 + r0) * K + seg * 8;
    const __nv_bfloat16* sBl = Blo + (size_t)(gn0 + r0) * K + seg * 8;
    uint32_t dsto = (uint32_t)(r0 * MMR + seg * 16);

    auto load_chunk = [&](int stage, int chunk) {
        uint32_t so = sbase + stage * MG_STAGE + dsto;
        size_t ko = (size_t)chunk * 64;
        #pragma unroll
        for (int j = 0; j < 2; j++) {
            cpasync16(so + j * (32 * MMR),              sAh + ko + (size_t)j * 32 * K);
            cpasync16(so + MG_ABYTES + j * (32 * MMR),  sAl + ko + (size_t)j * 32 * K);
        }
        #pragma unroll
        for (int j = 0; j < 4; j++) {
            cpasync16(so + 2 * MG_ABYTES + j * (32 * MMR),
                      sBh + ko + (size_t)j * 32 * K);
            cpasync16(so + 2 * MG_ABYTES + MG_BBYTES + j * (32 * MMR),
                      sBl + ko + (size_t)j * 32 * K);
        }
        CP_COMMIT();
    };

    float acc[2][4][4];
    #pragma unroll
    for (int i = 0; i < 2; i++)
        #pragma unroll
        for (int j = 0; j < 4; j++)
            #pragma unroll
            for (int e = 0; e < 4; e++) acc[i][j][e] = 0.f;

    load_chunk(0, 0);
    load_chunk(1, 1);

    int lrow = lane & 15;
    int lkb  = (lane >> 4) * 16;

    for (int i = 0; i < nch; i++) {
        if (i + 1 < nch) asm volatile("cp.async.wait_group 1;\n" ::: "memory");
        else             asm volatile("cp.async.wait_group 0;\n" ::: "memory");
        __syncthreads();

        uint32_t so = sbase + (i & 1) * MG_STAGE;
        uint32_t arow = so + (wm + lrow) * MMR;
        uint32_t brow = so + 2 * MG_ABYTES + (wn + lrow) * MMR;

        #pragma unroll
        for (int ks = 0; ks < 4; ks++) {
            uint32_t kb = (uint32_t)(ks * 32) + lkb;
            uint32_t ah[2][4], al[2][4], bh[2][4], bl[2][4];
            #pragma unroll
            for (int mt = 0; mt < 2; mt++) {
                ldm_x4(ah[mt], arow + mt * (16 * MMR) + kb);
                ldm_x4(al[mt], arow + MG_ABYTES + mt * (16 * MMR) + kb);
            }
            #pragma unroll
            for (int np = 0; np < 2; np++) {
                ldm_x4(bh[np], brow + np * (16 * MMR) + kb);
                ldm_x4(bl[np], brow + MG_BBYTES + np * (16 * MMR) + kb);
            }
            #pragma unroll
            for (int mt = 0; mt < 2; mt++)
                #pragma unroll
                for (int nt = 0; nt < 4; nt++) {
                    int np = nt >> 1, h = nt & 1;
                    mma16816(acc[mt][nt], ah[mt], bh[np][h], bh[np][h + 2]);
                }
            #pragma unroll
            for (int mt = 0; mt < 2; mt++)
                #pragma unroll
                for (int nt = 0; nt < 4; nt++) {
                    int np = nt >> 1, h = nt & 1;
                    mma16816(acc[mt][nt], al[mt], bh[np][h], bh[np][h + 2]);
                }
            #pragma unroll
            for (int mt = 0; mt < 2; mt++)
                #pragma unroll
                for (int nt = 0; nt < 4; nt++) {
                    int np = nt >> 1, h = nt & 1;
                    mma16816(acc[mt][nt], ah[mt], bl[np][h], bl[np][h + 2]);
                }
        }
        __syncthreads();
        if (i + 2 < nch) load_chunk(i & 1, i + 2);
    }

    int r  = lane >> 2;
    int c2 = (lane & 3) * 2;
    #pragma unroll
    for (int mt = 0; mt < 2; mt++) {
        #pragma unroll
        for (int nt = 0; nt < 4; nt++) {
            int m = gm0 + wm + mt * 16 + r;
            int n = gn0 + wn + nt * 8 + c2;
            float* d = acc[mt][nt];
            #pragma unroll
            for (int hh = 0; hh < 2; hh++) {
                int mm = m + hh * 8;
                float v0 = d[2*hh], v1 = d[2*hh + 1];
                if (mode == 2) {
                    v0 = gelu_exact(v0 + bias[n]);
                    v1 = gelu_exact(v1 + bias[n + 1]);
                    __nv_bfloat16 h0, l0, h1, l1;
                    split_bf16(v0, h0, l0); split_bf16(v1, h1, l1);
                    *(__nv_bfloat162*)(outhi + (size_t)mm * N + n) = __nv_bfloat162(h0, h1);
                    *(__nv_bfloat162*)(outlo + (size_t)mm * N + n) = __nv_bfloat162(l0, l1);
                } else {
                    if (mode != 3) { v0 += bias[n]; v1 += bias[n + 1]; }
                    if (mode == 1) {
                        const float2 rv = *(const float2*)(res + (size_t)mm * N + n);
                        v0 += rv.x; v1 += rv.y;
                    }
                    *(float2*)(outf + (size_t)mm * N + n) = make_float2(v0, v1);
                }
            }
        }
    }
}

// ---------------- tf32 single-product GEMM (head): BM=64, BN=128 -----------
// A in A-perm layout, B in B-perm layout; out plain fp32 [M][N].
#define TG_A 8192
#define TG_B 16384
#define TG_ST 24576
#define TG_SMEM (2*TG_ST)    // 49152

__global__ void __launch_bounds__(256, 2) k_tgemm(
    const float* __restrict__ Ap, const float* __restrict__ Bp,
    float* __restrict__ out, int M, int N, int K) {
    extern __shared__ char smem[];
    uint32_t sbase = smem_u32(smem);
    int tid = threadIdx.x, lane = tid & 31, warp = tid >> 5;
    int wm = (warp >> 2) * 32, wn = (warp & 3) * 32;
    int K8 = K >> 3;
    int nch = K >> 5;
    int gm16 = blockIdx.y * 4, gn16 = blockIdx.x * 8;
    int gm0 = blockIdx.y * 64, gn0 = blockIdx.x * 128;

    // per-thread cp.async sources (float4 units)
    int t0 = tid >> 5, ln = tid & 31;
    const float4* Ag0 = (const float4*)Ap +
        ((size_t)(gm16 + (t0 >> 2)) * K8 + (t0 & 3)) * 32 + ln;
    const float4* Ag1 = (const float4*)Ap +
        ((size_t)(gm16 + (t0 >> 2) + 2) * K8 + (t0 & 3)) * 32 + ln;
    const float4* Bg0 = (const float4*)Bp +
        ((size_t)(gn16 + (t0 >> 2)) * K8 + (t0 & 3)) * 32 + ln;
    const float4* Bg1 = (const float4*)Bp +
        ((size_t)(gn16 + (t0 >> 2) + 2) * K8 + (t0 & 3)) * 32 + ln;
    const float4* Bg2 = (const float4*)Bp +
        ((size_t)(gn16 + (t0 >> 2) + 4) * K8 + (t0 & 3)) * 32 + ln;
    const float4* Bg3 = (const float4*)Bp +
        ((size_t)(gn16 + (t0 >> 2) + 6) * K8 + (t0 & 3)) * 32 + ln;

    auto load_chunk = [&](int stage, int kc) {
        uint32_t st = sbase + stage * TG_ST;
        size_t ko = (size_t)kc * 128;           // 4 k8-tiles * 32 float4
        cpasync16(st + tid * 16,                 Ag0 + ko);
        cpasync16(st + (tid + 256) * 16,         Ag1 + ko);
        cpasync16(st + TG_A + tid * 16,          Bg0 + ko);
        cpasync16(st + TG_A + (tid + 256) * 16,  Bg1 + ko);
        cpasync16(st + TG_A + (tid + 512) * 16,  Bg2 + ko);
        cpasync16(st + TG_A + (tid + 768) * 16,  Bg3 + ko);
        CP_COMMIT();
    };

    float acc[2][4][4];
    #pragma unroll
    for (int i = 0; i < 2; i++)
        #pragma unroll
        for (int j = 0; j < 4; j++)
            #pragma unroll
            for (int e = 0; e < 4; e++) acc[i][j][e] = 0.f;

    load_chunk(0, 0);
    load_chunk(1, 1);

    int mtb = (warp >> 2) * 2;   // m16-tile base within block (0/2)
    int ntb = (warp & 3) * 2;    // n16-tile base within block (0..6)

    for (int i = 0; i < nch; i++) {
        if (i + 1 < nch) asm volatile("cp.async.wait_group 1;\n" ::: "memory");
        else             asm volatile("cp.async.wait_group 0;\n" ::: "memory");
        __syncthreads();

        uint32_t st = sbase + (i & 1) * TG_ST;
        #pragma unroll
        for (int k8 = 0; k8 < 4; k8++) {
            uint32_t a0[4], a1[4], b0[4], b1[4];
            lds128(a0, st + (uint32_t)(((mtb + 0) * 4 + k8) * 512) + lane * 16);
            lds128(a1, st + (uint32_t)(((mtb + 1) * 4 + k8) * 512) + lane * 16);
            lds128(b0, st + TG_A + (uint32_t)(((ntb + 0) * 4 + k8) * 512) + lane * 16);
            lds128(b1, st + TG_A + (uint32_t)(((ntb + 1) * 4 + k8) * 512) + lane * 16);
            mma_tf32(acc[0][0], a0, b0[0], b0[1]);
            mma_tf32(acc[0][1], a0, b0[2], b0[3]);
            mma_tf32(acc[0][2], a0, b1[0], b1[1]);
            mma_tf32(acc[0][3], a0, b1[2], b1[3]);
            mma_tf32(acc[1][0], a1, b0[0], b0[1]);
            mma_tf32(acc[1][1], a1, b0[2], b0[3]);
            mma_tf32(acc[1][2], a1, b1[0], b1[1]);
            mma_tf32(acc[1][3], a1, b1[2], b1[3]);
        }
        __syncthreads();
        if (i + 2 < nch) load_chunk(i & 1, i + 2);
    }

    int r  = lane >> 2;
    int c2 = (lane & 3) * 2;
    #pragma unroll
    for (int mt = 0; mt < 2; mt++) {
        #pragma unroll
        for (int nt = 0; nt < 4; nt++) {
            int m = gm0 + wm + mt * 16 + r;
            int n = gn0 + wn + nt * 8 + c2;
            float* d = acc[mt][nt];
            #pragma unroll
            for (int hh = 0; hh < 2; hh++) {
                int mm = m + hh * 8;
                *(float2*)(out + (size_t)mm * N + n) =
                    make_float2(d[2*hh], d[2*hh + 1]);
            }
        }
    }
}

// ---------------- flash-tiled causal attention -----------------------------
#define ASTR 68
#define ASMEM (4 * 64 * ASTR * 4)

__global__ void __launch_bounds__(256) k_fattn(
    const float* __restrict__ qkv,
    __nv_bfloat16* __restrict__ yh, __nv_bfloat16* __restrict__ yl) {
    extern __shared__ float sm[];
    float* Qs = sm;
    float* Ks = sm + 64 * ASTR;
    float* Vs = sm + 2 * 64 * ASTR;
    float* Ps = sm + 3 * 64 * ASTR;

    int q0 = blockIdx.x * 64, h = blockIdx.y, b = blockIdx.z;
    int tid = threadIdx.x, lane = tid & 31, warp = tid >> 5;
    int r = lane >> 2, c = lane & 3;
    int qrow = warp * 8 + r;
    int qglob = q0 + qrow;

    {
        const float4* g = (const float4*)qkv;
        float4* s4 = (float4*)Qs;
        for (int i = tid; i < 1024; i += 256) {
            int row = i >> 4, sg = i & 15;
            s4[row * 17 + sg] = g[((size_t)(b * Tz + q0 + row) * (3*Cz) + h * 64) / 4 + sg];
        }
    }

    float mrow = -1e30f, lrow = 0.f;
    float oacc[16];
    #pragma unroll
    for (int i = 0; i < 16; i++) oacc[i] = 0.f;

    int ntiles = (q0 >> 6) + 1;
    for (int t = 0; t < ntiles; t++) {
        __syncthreads();
        {
            const float4* g = (const float4*)qkv;
            float4* k4 = (float4*)Ks;
            float4* v4 = (float4*)Vs;
            for (int i = tid; i < 1024; i += 256) {
                int row = i >> 4, sg = i & 15;
                size_t gb = ((size_t)(b * Tz + t * 64 + row) * (3*Cz) + h * 64) / 4 + sg;
                k4[row * 17 + sg] = g[gb + Cz / 4];
                v4[row * 17 + sg] = g[gb + 2 * Cz / 4];
            }
        }
        __syncthreads();

        float s[16];
        #pragma unroll
        for (int kk = 0; kk < 16; kk++) s[kk] = 0.f;
        const float4* q4 = (const float4*)Qs + qrow * 17;
        const float4* k4b = (const float4*)Ks;
        #pragma unroll 4
        for (int d4 = 0; d4 < 16; d4++) {
            float4 qv = q4[d4];
            #pragma unroll
            for (int kk = 0; kk < 16; kk++) {
                float4 kv = k4b[(kk * 4 + c) * 17 + d4];
                s[kk] += qv.x * kv.x + qv.y * kv.y + qv.z * kv.z + qv.w * kv.w;
            }
        }
        bool maskt = (t == ntiles - 1);
        float tmax = -1e30f;
        #pragma unroll
        for (int kk = 0; kk < 16; kk++) {
            s[kk] *= 0.125f;
            if (maskt && (t * 64 + kk * 4 + c) > qglob) s[kk] = -1e30f;
            tmax = fmaxf(tmax, s[kk]);
        }
        tmax = fmaxf(tmax, __shfl_xor_sync(0xffffffffu, tmax, 1));
        tmax = fmaxf(tmax, __shfl_xor_sync(0xffffffffu, tmax, 2));
        float mnew = fmaxf(mrow, tmax);
        float scale = __expf(mrow - mnew);
        float psum = 0.f;
        #pragma unroll
        for (int kk = 0; kk < 16; kk++) {
            float p = __expf(s[kk] - mnew);
            s[kk] = p;
            psum += p;
            Ps[qrow * ASTR + kk * 4 + c] = p;
        }
        psum += __shfl_xor_sync(0xffffffffu, psum, 1);
        psum += __shfl_xor_sync(0xffffffffu, psum, 2);
        lrow = lrow * scale + psum;
        #pragma unroll
        for (int i = 0; i < 16; i++) oacc[i] *= scale;
        mrow = mnew;
        __syncwarp();

        const float4* p4 = (const float4*)Ps + qrow * 17;
        const float4* v4b = (const float4*)Vs;
        #pragma unroll 2
        for (int kq = 0; kq < 16; kq++) {
            float4 pv = p4[kq];
            #pragma unroll
            for (int j = 0; j < 4; j++) {
                float pj = (j == 0) ? pv.x : (j == 1) ? pv.y : (j == 2) ? pv.z : pv.w;
                const float4* vr = v4b + (kq * 4 + j) * 17 + c * 4;
                #pragma unroll
                for (int e = 0; e < 4; e++) {
                    float4 vv = vr[e];
                    oacc[e*4+0] += pj * vv.x;
                    oacc[e*4+1] += pj * vv.y;
                    oacc[e*4+2] += pj * vv.z;
                    oacc[e*4+3] += pj * vv.w;
                }
            }
        }
    }

    float inv = 1.0f / lrow;
    size_t base = (size_t)(b * Tz + qglob) * Cz + h * 64 + c * 16;
    #pragma unroll
    for (int g = 0; g < 8; g++) {
        float v0 = oacc[2*g] * inv, v1 = oacc[2*g+1] * inv;
        __nv_bfloat16 h0, l0, h1, l1;
        split_bf16(v0, h0, l0); split_bf16(v1, h1, l1);
        *(__nv_bfloat162*)(yh + base + 2*g) = __nv_bfloat162(h0, h1);
        *(__nv_bfloat162*)(yl + base + 2*g) = __nv_bfloat162(l0, l1);
    }
}

// ---------------- driver ----------------------------------------------------
extern "C" void kernel_launch(void* const* d_in, const int* in_sizes, int n_in,
                              void* d_out, int out_size) {
    const int*   idx    = (const int*)  d_in[0];
    const float* wte    = (const float*)d_in[1];
    const float* wpe    = (const float*)d_in[2];
    const float* ln1_w  = (const float*)d_in[3];
    const float* ln1_b  = (const float*)d_in[4];
    const float* attn_w = (const float*)d_in[5];
    const float* attn_b = (const float*)d_in[6];
    const float* proj_w = (const float*)d_in[7];
    const float* proj_b = (const float*)d_in[8];
    const float* ln2_w  = (const float*)d_in[9];
    const float* ln2_b  = (const float*)d_in[10];
    const float* fc_w   = (const float*)d_in[11];
    const float* fc_b   = (const float*)d_in[12];
    const float* mlp_w  = (const float*)d_in[13];
    const float* mlp_b  = (const float*)d_in[14];
    const float* lnf_w  = (const float*)d_in[15];
    const float* lnf_b  = (const float*)d_in[16];
    const float* head_w = (const float*)d_in[17];
    float* out = (float*)d_out;

    float *px, *pqkv, *pwht, *plnt;
    __nv_bfloat16 *plnh, *plnl, *pyh, *pyl, *phh, *phl;
    __nv_bfloat16 *wqh, *wql, *wph, *wpl, *wfh, *wfl, *wmh, *wml;
    cudaGetSymbolAddress((void**)&px,   g_x);
    cudaGetSymbolAddress((void**)&pqkv, g_qkv);
    cudaGetSymbolAddress((void**)&plnh, g_lnh);
    cudaGetSymbolAddress((void**)&plnl, g_lnl);
    cudaGetSymbolAddress((void**)&pyh,  g_yh);
    cudaGetSymbolAddress((void**)&pyl,  g_yl);
    cudaGetSymbolAddress((void**)&phh,  g_hh);
    cudaGetSymbolAddress((void**)&phl,  g_hl);
    cudaGetSymbolAddress((void**)&wqh,  g_wqkv_h);
    cudaGetSymbolAddress((void**)&wql,  g_wqkv_l);
    cudaGetSymbolAddress((void**)&wph,  g_wproj_h);
    cudaGetSymbolAddress((void**)&wpl,  g_wproj_l);
    cudaGetSymbolAddress((void**)&wfh,  g_wfc_h);
    cudaGetSymbolAddress((void**)&wfl,  g_wfc_l);
    cudaGetSymbolAddress((void**)&wmh,  g_wmlp_h);
    cudaGetSymbolAddress((void**)&wml,  g_wmlp_l);
    cudaGetSymbolAddress((void**)&pwht, g_whead_t);
    cudaGetSymbolAddress((void**)&plnt, g_lnt);

    cudaFuncSetAttribute(k_mgemm, cudaFuncAttributeMaxDynamicSharedMemorySize, MG_SMEM);
    cudaFuncSetAttribute(k_tgemm, cudaFuncAttributeMaxDynamicSharedMemorySize, TG_SMEM);
    cudaFuncSetAttribute(k_fattn, cudaFuncAttributeMaxDynamicSharedMemorySize, ASMEM);

    dim3 tp(32, 8);
    // ---- launches 1-3 chosen so my launch #4 (= ncu capture slot) is k_fattn
    k_wprep<<<dim3(3*Cz/32, Cz/32), tp>>>(attn_w, wqh, wql, Cz, 3*Cz);     // 1
    k_embed_ln<<<BT, 256>>>(idx, wte, wpe, ln1_w, ln1_b, plnh, plnl);      // 2
    k_mgemm<<<dim3(3*Cz/128, BT/64), 256, MG_SMEM>>>(                      // 3
        plnh, plnl, wqh, wql, attn_b, nullptr, pqkv, nullptr, nullptr,
        BT, 3*Cz, Cz, 0);
    k_fattn<<<dim3(Tz/64, Hz, Bz), 256, ASMEM>>>(pqkv, pyh, pyl);          // 4 (ncu)

    // remaining weight preps
    k_wprep<<<dim3(Cz/32, Cz/32), tp>>>(proj_w, wph, wpl, Cz, Cz);
    k_wprep<<<dim3(4*Cz/32, Cz/32), tp>>>(fc_w, wfh, wfl, Cz, 4*Cz);
    k_wprep<<<dim3(Cz/32, 4*Cz/32), tp>>>(mlp_w, wmh, wml, 4*Cz, Cz);
    for (int l = 1; l < Lz; l++) {
        k_wprep<<<dim3(3*Cz/32, Cz/32), tp>>>(attn_w + (size_t)l*Cz*3*Cz,
            wqh + (size_t)l*3*Cz*Cz, wql + (size_t)l*3*Cz*Cz, Cz, 3*Cz);
        k_wprep<<<dim3(Cz/32, Cz/32), tp>>>(proj_w + (size_t)l*Cz*Cz,
            wph + (size_t)l*Cz*Cz, wpl + (size_t)l*Cz*Cz, Cz, Cz);
        k_wprep<<<dim3(4*Cz/32, Cz/32), tp>>>(fc_w + (size_t)l*Cz*4*Cz,
            wfh + (size_t)l*4*Cz*Cz, wfl + (size_t)l*4*Cz*Cz, Cz, 4*Cz);
        k_wprep<<<dim3(Cz/32, 4*Cz/32), tp>>>(mlp_w + (size_t)l*4*Cz*Cz,
            wmh + (size_t)l*Cz*4*Cz, wml + (size_t)l*Cz*4*Cz, 4*Cz, Cz);
    }
    k_wprep_head<<<dim3(Vz/32, Cz/32), tp>>>(head_w, pwht);

    for (int l = 0; l < Lz; l++) {
        const float* ab = attn_b + (size_t)l * 3 * Cz;
        const float* pb = proj_b + (size_t)l * Cz;
        const float* fb = fc_b   + (size_t)l * 4 * Cz;
        const float* mb = mlp_b  + (size_t)l * Cz;

        if (l > 0) {
            k_ln<<<BT, 256>>>(px, ln1_w + (size_t)l*Cz, ln1_b + (size_t)l*Cz, plnh, plnl);
            k_mgemm<<<dim3(3*Cz/128, BT/64), 256, MG_SMEM>>>(
                plnh, plnl, wqh + (size_t)l*3*Cz*Cz, wql + (size_t)l*3*Cz*Cz,
                ab, nullptr, pqkv, nullptr, nullptr, BT, 3*Cz, Cz, 0);
            k_fattn<<<dim3(Tz/64, Hz, Bz), 256, ASMEM>>>(pqkv, pyh, pyl);
        }
        // x += y @ Wproj + b       [4096, 768]
        k_mgemm<<<dim3(Cz/128, BT/64), 256, MG_SMEM>>>(
            pyh, pyl, wph + (size_t)l*Cz*Cz, wpl + (size_t)l*Cz*Cz,
            pb, px, px, nullptr, nullptr, BT, Cz, Cz, 1);
        k_ln<<<BT, 256>>>(px, ln2_w + (size_t)l*Cz, ln2_b + (size_t)l*Cz, plnh, plnl);
        // h = gelu(ln2 @ Wfc + b)  [4096, 3072]
        k_mgemm<<<dim3(4*Cz/128, BT/64), 256, MG_SMEM>>>(
            plnh, plnl, wfh + (size_t)l*4*Cz*Cz, wfl + (size_t)l*4*Cz*Cz,
            fb, nullptr, nullptr, phh, phl, BT, 4*Cz, Cz, 2);
        // x += h @ Wmlp + b        [4096, 768], K=3072
        k_mgemm<<<dim3(Cz/128, BT/64), 256, MG_SMEM>>>(
            phh, phl, wmh + (size_t)l*Cz*4*Cz, wml + (size_t)l*Cz*4*Cz,
            mb, px, px, nullptr, nullptr, BT, Cz, 4*Cz, 1);
    }

    // final layernorm -> A-perm tf32, then tf32 head GEMM
    k_lnp<<<BT, 256>>>(px, lnf_w, lnf_b, plnt);
    k_tgemm<<<dim3(Vz/128, BT/64), 256, TG_SMEM>>>(plnt, pwht, out, BT, Vz, Cz);
}

// round 11
// speedup vs baseline: 1.8812x; 1.7295x over previous
#include <cuda_runtime.h>
#include <cuda_bf16.h>
#include <math.h>
#include <stdint.h>

#define Bz 4
#define Tz 1024
#define Cz 768
#define Hz 12
#define HDz 64
#define Lz 6
#define Vz 32000
#define BT (Bz*Tz)

// ---------------- scratch (static device globals; no allocations) ----------
__device__ float g_x[BT*Cz];                     // residual stream (fp32)
__device__ __nv_bfloat16 g_lnh[BT*Cz], g_lnl[BT*Cz];     // layernorm out hi/lo
__device__ __nv_bfloat16 g_qkvh[BT*3*Cz], g_qkvl[BT*3*Cz]; // qkv bf16 hi/lo
__device__ __nv_bfloat16 g_yh[BT*Cz], g_yl[BT*Cz];       // attention out hi/lo
__device__ __nv_bfloat16 g_hh[BT*4*Cz], g_hl[BT*4*Cz];   // MLP hidden hi/lo
// transposed bf16 hi/lo weights: Wt[N,K] row-major (K contiguous)
__device__ __nv_bfloat16 g_wqkv_h[Lz*3*Cz*Cz], g_wqkv_l[Lz*3*Cz*Cz];
__device__ __nv_bfloat16 g_wproj_h[Lz*Cz*Cz],  g_wproj_l[Lz*Cz*Cz];
__device__ __nv_bfloat16 g_wfc_h[Lz*4*Cz*Cz],  g_wfc_l[Lz*4*Cz*Cz];
__device__ __nv_bfloat16 g_wmlp_h[Lz*Cz*4*Cz], g_wmlp_l[Lz*Cz*4*Cz];
// tf32 head path: fragment-ready permuted layouts
__device__ float g_whead_t[(size_t)Vz*Cz];       // B-perm tf32
__device__ float g_lnt[BT*Cz];                   // A-perm tf32 (final LN out)

// ---------------- helpers ---------------------------------------------------
__device__ __forceinline__ uint32_t smem_u32(const void* p) {
    uint32_t a;
    asm("{ .reg .u64 t; cvta.to.shared.u64 t, %1; cvt.u32.u64 %0, t; }"
        : "=r"(a) : "l"(p));
    return a;
}
__device__ __forceinline__ void cpasync16(uint32_t s, const void* g) {
    asm volatile("cp.async.cg.shared.global [%0], [%1], 16;\n" :: "r"(s), "l"(g));
}
#define CP_COMMIT() asm volatile("cp.async.commit_group;\n" ::: "memory")

__device__ __forceinline__ void ldm_x4(uint32_t* r, uint32_t addr) {
    asm volatile("ldmatrix.sync.aligned.m8n8.x4.shared.b16 {%0,%1,%2,%3}, [%4];"
        : "=r"(r[0]), "=r"(r[1]), "=r"(r[2]), "=r"(r[3]) : "r"(addr));
}
__device__ __forceinline__ void ldm_x4t(uint32_t* r, uint32_t addr) {
    asm volatile("ldmatrix.sync.aligned.m8n8.x4.trans.shared.b16 {%0,%1,%2,%3}, [%4];"
        : "=r"(r[0]), "=r"(r[1]), "=r"(r[2]), "=r"(r[3]) : "r"(addr));
}
__device__ __forceinline__ void lds128(uint32_t* r, uint32_t addr) {
    asm volatile("ld.shared.v4.b32 {%0,%1,%2,%3}, [%4];"
        : "=r"(r[0]), "=r"(r[1]), "=r"(r[2]), "=r"(r[3]) : "r"(addr));
}
__device__ __forceinline__ void mma16816(float* d, const uint32_t* a,
                                         uint32_t b0, uint32_t b1) {
    asm volatile("mma.sync.aligned.m16n8k16.row.col.f32.bf16.bf16.f32 "
        "{%0,%1,%2,%3}, {%4,%5,%6,%7}, {%8,%9}, {%0,%1,%2,%3};"
        : "+f"(d[0]), "+f"(d[1]), "+f"(d[2]), "+f"(d[3])
        : "r"(a[0]), "r"(a[1]), "r"(a[2]), "r"(a[3]), "r"(b0), "r"(b1));
}
__device__ __forceinline__ void mma_tf32(float* d, const uint32_t* a,
                                         uint32_t b0, uint32_t b1) {
    asm volatile("mma.sync.aligned.m16n8k8.row.col.f32.tf32.tf32.f32 "
        "{%0,%1,%2,%3}, {%4,%5,%6,%7}, {%8,%9}, {%0,%1,%2,%3};"
        : "+f"(d[0]), "+f"(d[1]), "+f"(d[2]), "+f"(d[3])
        : "r"(a[0]), "r"(a[1]), "r"(a[2]), "r"(a[3]), "r"(b0), "r"(b1));
}
__device__ __forceinline__ float tf32r(float x) {
    uint32_t r;
    asm("cvt.rna.tf32.f32 %0, %1;" : "=r"(r) : "f"(x));
    return __uint_as_float(r);
}
__device__ __forceinline__ void split_bf16(float v, __nv_bfloat16& hi, __nv_bfloat16& lo) {
    hi = __float2bfloat16(v);
    lo = __float2bfloat16(v - __bfloat162float(hi));
}
__device__ __forceinline__ uint32_t pack_hi2(float a, float b) {
    __nv_bfloat162 p(__float2bfloat16(a), __float2bfloat16(b));
    return *(uint32_t*)&p;
}
__device__ __forceinline__ uint32_t pack_lo2(float a, float b) {
    __nv_bfloat16 ha = __float2bfloat16(a), hb = __float2bfloat16(b);
    __nv_bfloat162 p(__float2bfloat16(a - __bfloat162float(ha)),
                     __float2bfloat16(b - __bfloat162float(hb)));
    return *(uint32_t*)&p;
}
__device__ __forceinline__ float gelu_exact(float v) {
    return 0.5f * v * (1.0f + erff(v * 0.70710678118654752f));
}

// permuted-layout index helpers (tf32 fragment-ready)
__device__ __forceinline__ size_t aperm_off(int m, int k, int K8) {
    return ((size_t)(m >> 4) * K8 + (k >> 3)) * 128
         + ((m & 7) * 4 + (k & 3)) * 4 + ((m >> 3) & 1) + 2 * ((k >> 2) & 1);
}
__device__ __forceinline__ size_t bperm_off(int n, int k, int K8) {
    return ((size_t)(n >> 4) * K8 + (k >> 3)) * 128
         + ((n & 7) * 4 + (k & 3)) * 4 + ((k >> 2) & 1) + 2 * ((n >> 3) & 1);
}

// ---------------- fused embed + layer-0 ln1 --------------------------------
__global__ void k_embed_ln(const int* __restrict__ idx,
                           const float* __restrict__ wte,
                           const float* __restrict__ wpe,
                           const float* __restrict__ w,
                           const float* __restrict__ b,
                           __nv_bfloat16* __restrict__ ohi,
                           __nv_bfloat16* __restrict__ olo) {
    int row = blockIdx.x;
    int tid = threadIdx.x;
    int t = row % Tz;
    int tok = idx[row];
    const float* we = wte + (size_t)tok * Cz;
    const float* pe = wpe + (size_t)t * Cz;
    float v0 = we[tid] + pe[tid];
    float v1 = we[tid + 256] + pe[tid + 256];
    float v2 = we[tid + 512] + pe[tid + 512];
    size_t base = (size_t)row * Cz;
    g_x[base + tid] = v0; g_x[base + tid + 256] = v1; g_x[base + tid + 512] = v2;

    __shared__ float red[256];
    red[tid] = v0 + v1 + v2;
    __syncthreads();
    #pragma unroll
    for (int off = 128; off > 0; off >>= 1) {
        if (tid < off) red[tid] += red[tid + off];
        __syncthreads();
    }
    float mean = red[0] * (1.0f / Cz);
    __syncthreads();
    float d0 = v0 - mean, d1 = v1 - mean, d2 = v2 - mean;
    red[tid] = d0*d0 + d1*d1 + d2*d2;
    __syncthreads();
    #pragma unroll
    for (int off = 128; off > 0; off >>= 1) {
        if (tid < off) red[tid] += red[tid + off];
        __syncthreads();
    }
    float rstd = rsqrtf(red[0] * (1.0f / Cz) + 1e-5f);
    float r0 = d0 * rstd * w[tid]       + b[tid];
    float r1 = d1 * rstd * w[tid + 256] + b[tid + 256];
    float r2 = d2 * rstd * w[tid + 512] + b[tid + 512];
    __nv_bfloat16 hi, lo;
    split_bf16(r0, hi, lo); ohi[base + tid]       = hi; olo[base + tid]       = lo;
    split_bf16(r1, hi, lo); ohi[base + tid + 256] = hi; olo[base + tid + 256] = lo;
    split_bf16(r2, hi, lo); ohi[base + tid + 512] = hi; olo[base + tid + 512] = lo;
}

// ---------------- weight transpose + bf16 hi/lo split ----------------------
__global__ void k_wprep(const float* __restrict__ W,
                        __nv_bfloat16* __restrict__ Whi,
                        __nv_bfloat16* __restrict__ Wlo, int K, int N) {
    __shared__ float t[32][33];
    int n0 = blockIdx.x * 32, k0 = blockIdx.y * 32;
    int tx = threadIdx.x, ty = threadIdx.y;   // 32 x 8
    #pragma unroll
    for (int j = 0; j < 32; j += 8)
        t[ty + j][tx] = W[(size_t)(k0 + ty + j) * N + n0 + tx];
    __syncthreads();
    #pragma unroll
    for (int j = 0; j < 32; j += 8) {
        float v = t[tx][ty + j];
        __nv_bfloat16 hi, lo; split_bf16(v, hi, lo);
        size_t o = (size_t)(n0 + ty + j) * K + k0 + tx;
        Whi[o] = hi; Wlo[o] = lo;
    }
}

// ---------------- head weight -> B-perm tf32 -------------------------------
__global__ void k_wprep_head(const float* __restrict__ W,   // [Cz][Vz]
                             float* __restrict__ Wp) {
    __shared__ float t[32][33];
    int n0 = blockIdx.x * 32, k0 = blockIdx.y * 32;
    int tx = threadIdx.x, ty = threadIdx.y;
    #pragma unroll
    for (int j = 0; j < 32; j += 8)
        t[ty + j][tx] = W[(size_t)(k0 + ty + j) * Vz + n0 + tx];
    __syncthreads();
    #pragma unroll
    for (int j = 0; j < 32; j += 8) {
        int n = n0 + ty + j, k = k0 + tx;
        Wp[bperm_off(n, k, Cz >> 3)] = tf32r(t[tx][ty + j]);
    }
}

// ---------------- layernorm -> bf16 hi/lo ----------------------------------
__global__ void k_ln(const float* __restrict__ x,
                     const float* __restrict__ w,
                     const float* __restrict__ b,
                     __nv_bfloat16* __restrict__ ohi,
                     __nv_bfloat16* __restrict__ olo) {
    int row = blockIdx.x;
    int tid = threadIdx.x;
    const float* xr = x + (size_t)row * Cz;
    float v0 = xr[tid], v1 = xr[tid + 256], v2 = xr[tid + 512];

    __shared__ float red[256];
    red[tid] = v0 + v1 + v2;
    __syncthreads();
    #pragma unroll
    for (int off = 128; off > 0; off >>= 1) {
        if (tid < off) red[tid] += red[tid + off];
        __syncthreads();
    }
    float mean = red[0] * (1.0f / Cz);
    __syncthreads();
    float d0 = v0 - mean, d1 = v1 - mean, d2 = v2 - mean;
    red[tid] = d0*d0 + d1*d1 + d2*d2;
    __syncthreads();
    #pragma unroll
    for (int off = 128; off > 0; off >>= 1) {
        if (tid < off) red[tid] += red[tid + off];
        __syncthreads();
    }
    float rstd = rsqrtf(red[0] * (1.0f / Cz) + 1e-5f);

    size_t base = (size_t)row * Cz;
    float r0 = d0 * rstd * w[tid]       + b[tid];
    float r1 = d1 * rstd * w[tid + 256] + b[tid + 256];
    float r2 = d2 * rstd * w[tid + 512] + b[tid + 512];
    __nv_bfloat16 hi, lo;
    split_bf16(r0, hi, lo); ohi[base + tid]       = hi; olo[base + tid]       = lo;
    split_bf16(r1, hi, lo); ohi[base + tid + 256] = hi; olo[base + tid + 256] = lo;
    split_bf16(r2, hi, lo); ohi[base + tid + 512] = hi; olo[base + tid + 512] = lo;
}

// ---------------- final layernorm -> A-perm tf32 ---------------------------
__global__ void k_lnp(const float* __restrict__ x,
                      const float* __restrict__ w,
                      const float* __restrict__ b,
                      float* __restrict__ op) {
    int row = blockIdx.x;
    int tid = threadIdx.x;
    const float* xr = x + (size_t)row * Cz;
    float v0 = xr[tid], v1 = xr[tid + 256], v2 = xr[tid + 512];

    __shared__ float red[256];
    red[tid] = v0 + v1 + v2;
    __syncthreads();
    #pragma unroll
    for (int off = 128; off > 0; off >>= 1) {
        if (tid < off) red[tid] += red[tid + off];
        __syncthreads();
    }
    float mean = red[0] * (1.0f / Cz);
    __syncthreads();
    float d0 = v0 - mean, d1 = v1 - mean, d2 = v2 - mean;
    red[tid] = d0*d0 + d1*d1 + d2*d2;
    __syncthreads();
    #pragma unroll
    for (int off = 128; off > 0; off >>= 1) {
        if (tid < off) red[tid] += red[tid + off];
        __syncthreads();
    }
    float rstd = rsqrtf(red[0] * (1.0f / Cz) + 1e-5f);

    int K8 = Cz >> 3;
    op[aperm_off(row, tid,       K8)] = tf32r(d0 * rstd * w[tid]       + b[tid]);
    op[aperm_off(row, tid + 256, K8)] = tf32r(d1 * rstd * w[tid + 256] + b[tid + 256]);
    op[aperm_off(row, tid + 512, K8)] = tf32r(d2 * rstd * w[tid + 512] + b[tid + 512]);
}

// ---------------- bf16 mma.sync GEMM: BM=64, BN=128 ------------------------
// mode: 0 unused | 1 = +bias+res->fp32 | 2 = gelu(+bias)->bf16 hi/lo
//       3 = plain->fp32 | 4 = +bias->bf16 hi/lo
#define MMR 144
#define MG_ABYTES (64*MMR)
#define MG_BBYTES (128*MMR)
#define MG_STAGE (2*MG_ABYTES + 2*MG_BBYTES)   // 55296
#define MG_SMEM (2*MG_STAGE)                   // 110592

__global__ void __launch_bounds__(256, 2) k_mgemm(
    const __nv_bfloat16* __restrict__ Ahi, const __nv_bfloat16* __restrict__ Alo,
    const __nv_bfloat16* __restrict__ Bhi, const __nv_bfloat16* __restrict__ Blo,
    const float* __restrict__ bias, const float* res,
    float* outf, __nv_bfloat16* outhi, __nv_bfloat16* outlo,
    int M, int N, int K, int mode) {
    extern __shared__ char smem[];
    uint32_t sbase = smem_u32(smem);
    int tid = threadIdx.x, lane = tid & 31, warp = tid >> 5;
    int wm = (warp >> 2) * 32;
    int wn = (warp & 3) * 32;
    int gn0 = blockIdx.x * 128, gm0 = blockIdx.y * 64;
    int nch = K >> 6;

    int r0 = tid >> 3, seg = tid & 7;
    const __nv_bfloat16* sAh = Ahi + (size_t)(gm0 + r0) * K + seg * 8;
    const __nv_bfloat16* sAl = Alo + (size_t)(gm0 + r0) * K + seg * 8;
    const __nv_bfloat16* sBh = Bhi + (size_t)(gn0 + r0) * K + seg * 8;
    const __nv_bfloat16* sBl = Blo + (size_t)(gn0 + r0) * K + seg * 8;
    uint32_t dsto = (uint32_t)(r0 * MMR + seg * 16);

    auto load_chunk = [&](int stage, int chunk) {
        uint32_t so = sbase + stage * MG_STAGE + dsto;
        size_t ko = (size_t)chunk * 64;
        #pragma unroll
        for (int j = 0; j < 2; j++) {
            cpasync16(so + j * (32 * MMR),              sAh + ko + (size_t)j * 32 * K);
            cpasync16(so + MG_ABYTES + j * (32 * MMR),  sAl + ko + (size_t)j * 32 * K);
        }
        #pragma unroll
        for (int j = 0; j < 4; j++) {
            cpasync16(so + 2 * MG_ABYTES + j * (32 * MMR),
                      sBh + ko + (size_t)j * 32 * K);
            cpasync16(so + 2 * MG_ABYTES + MG_BBYTES + j * (32 * MMR),
                      sBl + ko + (size_t)j * 32 * K);
        }
        CP_COMMIT();
    };

    float acc[2][4][4];
    #pragma unroll
    for (int i = 0; i < 2; i++)
        #pragma unroll
        for (int j = 0; j < 4; j++)
            #pragma unroll
            for (int e = 0; e < 4; e++) acc[i][j][e] = 0.f;

    load_chunk(0, 0);
    load_chunk(1, 1);

    int lrow = lane & 15;
    int lkb  = (lane >> 4) * 16;

    for (int i = 0; i < nch; i++) {
        if (i + 1 < nch) asm volatile("cp.async.wait_group 1;\n" ::: "memory");
        else             asm volatile("cp.async.wait_group 0;\n" ::: "memory");
        __syncthreads();

        uint32_t so = sbase + (i & 1) * MG_STAGE;
        uint32_t arow = so + (wm + lrow) * MMR;
        uint32_t brow = so + 2 * MG_ABYTES + (wn + lrow) * MMR;

        #pragma unroll
        for (int ks = 0; ks < 4; ks++) {
            uint32_t kb = (uint32_t)(ks * 32) + lkb;
            uint32_t ah[2][4], al[2][4], bh[2][4], bl[2][4];
            #pragma unroll
            for (int mt = 0; mt < 2; mt++) {
                ldm_x4(ah[mt], arow + mt * (16 * MMR) + kb);
                ldm_x4(al[mt], arow + MG_ABYTES + mt * (16 * MMR) + kb);
            }
            #pragma unroll
            for (int np = 0; np < 2; np++) {
                ldm_x4(bh[np], brow + np * (16 * MMR) + kb);
                ldm_x4(bl[np], brow + MG_BBYTES + np * (16 * MMR) + kb);
            }
            #pragma unroll
            for (int mt = 0; mt < 2; mt++)
                #pragma unroll
                for (int nt = 0; nt < 4; nt++) {
                    int np = nt >> 1, h = nt & 1;
                    mma16816(acc[mt][nt], ah[mt], bh[np][h], bh[np][h + 2]);
                }
            #pragma unroll
            for (int mt = 0; mt < 2; mt++)
                #pragma unroll
                for (int nt = 0; nt < 4; nt++) {
                    int np = nt >> 1, h = nt & 1;
                    mma16816(acc[mt][nt], al[mt], bh[np][h], bh[np][h + 2]);
                }
            #pragma unroll
            for (int mt = 0; mt < 2; mt++)
                #pragma unroll
                for (int nt = 0; nt < 4; nt++) {
                    int np = nt >> 1, h = nt & 1;
                    mma16816(acc[mt][nt], ah[mt], bl[np][h], bl[np][h + 2]);
                }
        }
        __syncthreads();
        if (i + 2 < nch) load_chunk(i & 1, i + 2);
    }

    int r  = lane >> 2;
    int c2 = (lane & 3) * 2;
    #pragma unroll
    for (int mt = 0; mt < 2; mt++) {
        #pragma unroll
        for (int nt = 0; nt < 4; nt++) {
            int m = gm0 + wm + mt * 16 + r;
            int n = gn0 + wn + nt * 8 + c2;
            float* d = acc[mt][nt];
            #pragma unroll
            for (int hh = 0; hh < 2; hh++) {
                int mm = m + hh * 8;
                float v0 = d[2*hh], v1 = d[2*hh + 1];
                if (mode == 2 || mode == 4) {
                    v0 += bias[n]; v1 += bias[n + 1];
                    if (mode == 2) { v0 = gelu_exact(v0); v1 = gelu_exact(v1); }
                    __nv_bfloat16 h0, l0, h1, l1;
                    split_bf16(v0, h0, l0); split_bf16(v1, h1, l1);
                    *(__nv_bfloat162*)(outhi + (size_t)mm * N + n) = __nv_bfloat162(h0, h1);
                    *(__nv_bfloat162*)(outlo + (size_t)mm * N + n) = __nv_bfloat162(l0, l1);
                } else {
                    if (mode != 3) { v0 += bias[n]; v1 += bias[n + 1]; }
                    if (mode == 1) {
                        const float2 rv = *(const float2*)(res + (size_t)mm * N + n);
                        v0 += rv.x; v1 += rv.y;
                    }
                    *(float2*)(outf + (size_t)mm * N + n) = make_float2(v0, v1);
                }
            }
        }
    }
}

// ---------------- tf32 single-product GEMM (head) --------------------------
#define TG_A 8192
#define TG_ST 24576
#define TG_SMEM (2*TG_ST)

__global__ void __launch_bounds__(256, 2) k_tgemm(
    const float* __restrict__ Ap, const float* __restrict__ Bp,
    float* __restrict__ out, int M, int N, int K) {
    extern __shared__ char smem[];
    uint32_t sbase = smem_u32(smem);
    int tid = threadIdx.x, lane = tid & 31, warp = tid >> 5;
    int wm = (warp >> 2) * 32, wn = (warp & 3) * 32;
    int K8 = K >> 3;
    int nch = K >> 5;
    int gm16 = blockIdx.y * 4, gn16 = blockIdx.x * 8;
    int gm0 = blockIdx.y * 64, gn0 = blockIdx.x * 128;

    int t0 = tid >> 5, ln = tid & 31;
    const float4* Ag0 = (const float4*)Ap +
        ((size_t)(gm16 + (t0 >> 2)) * K8 + (t0 & 3)) * 32 + ln;
    const float4* Ag1 = (const float4*)Ap +
        ((size_t)(gm16 + (t0 >> 2) + 2) * K8 + (t0 & 3)) * 32 + ln;
    const float4* Bg0 = (const float4*)Bp +
        ((size_t)(gn16 + (t0 >> 2)) * K8 + (t0 & 3)) * 32 + ln;
    const float4* Bg1 = (const float4*)Bp +
        ((size_t)(gn16 + (t0 >> 2) + 2) * K8 + (t0 & 3)) * 32 + ln;
    const float4* Bg2 = (const float4*)Bp +
        ((size_t)(gn16 + (t0 >> 2) + 4) * K8 + (t0 & 3)) * 32 + ln;
    const float4* Bg3 = (const float4*)Bp +
        ((size_t)(gn16 + (t0 >> 2) + 6) * K8 + (t0 & 3)) * 32 + ln;

    auto load_chunk = [&](int stage, int kc) {
        uint32_t st = sbase + stage * TG_ST;
        size_t ko = (size_t)kc * 128;
        cpasync16(st + tid * 16,                 Ag0 + ko);
        cpasync16(st + (tid + 256) * 16,         Ag1 + ko);
        cpasync16(st + TG_A + tid * 16,          Bg0 + ko);
        cpasync16(st + TG_A + (tid + 256) * 16,  Bg1 + ko);
        cpasync16(st + TG_A + (tid + 512) * 16,  Bg2 + ko);
        cpasync16(st + TG_A + (tid + 768) * 16,  Bg3 + ko);
        CP_COMMIT();
    };

    float acc[2][4][4];
    #pragma unroll
    for (int i = 0; i < 2; i++)
        #pragma unroll
        for (int j = 0; j < 4; j++)
            #pragma unroll
            for (int e = 0; e < 4; e++) acc[i][j][e] = 0.f;

    load_chunk(0, 0);
    load_chunk(1, 1);

    int mtb = (warp >> 2) * 2;
    int ntb = (warp & 3) * 2;

    for (int i = 0; i < nch; i++) {
        if (i + 1 < nch) asm volatile("cp.async.wait_group 1;\n" ::: "memory");
        else             asm volatile("cp.async.wait_group 0;\n" ::: "memory");
        __syncthreads();

        uint32_t st = sbase + (i & 1) * TG_ST;
        #pragma unroll
        for (int k8 = 0; k8 < 4; k8++) {
            uint32_t a0[4], a1[4], b0[4], b1[4];
            lds128(a0, st + (uint32_t)(((mtb + 0) * 4 + k8) * 512) + lane * 16);
            lds128(a1, st + (uint32_t)(((mtb + 1) * 4 + k8) * 512) + lane * 16);
            lds128(b0, st + TG_A + (uint32_t)(((ntb + 0) * 4 + k8) * 512) + lane * 16);
            lds128(b1, st + TG_A + (uint32_t)(((ntb + 1) * 4 + k8) * 512) + lane * 16);
            mma_tf32(acc[0][0], a0, b0[0], b0[1]);
            mma_tf32(acc[0][1], a0, b0[2], b0[3]);
            mma_tf32(acc[0][2], a0, b1[0], b1[1]);
            mma_tf32(acc[0][3], a0, b1[2], b1[3]);
            mma_tf32(acc[1][0], a1, b0[0], b0[1]);
            mma_tf32(acc[1][1], a1, b0[2], b0[3]);
            mma_tf32(acc[1][2], a1, b1[0], b1[1]);
            mma_tf32(acc[1][3], a1, b1[2], b1[3]);
        }
        __syncthreads();
        if (i + 2 < nch) load_chunk(i & 1, i + 2);
    }

    int r  = lane >> 2;
    int c2 = (lane & 3) * 2;
    #pragma unroll
    for (int mt = 0; mt < 2; mt++) {
        #pragma unroll
        for (int nt = 0; nt < 4; nt++) {
            int m = gm0 + wm + mt * 16 + r;
            int n = gn0 + wn + nt * 8 + c2;
            float* d = acc[mt][nt];
            #pragma unroll
            for (int hh = 0; hh < 2; hh++) {
                int mm = m + hh * 8;
                *(float2*)(out + (size_t)mm * N + n) =
                    make_float2(d[2*hh], d[2*hh + 1]);
            }
        }
    }
}

// ---------------- tensor-core flash attention ------------------------------
// CTA = 128 queries x (h, b); 8 warps, warp = 16 query rows.
// K tiles of 64 keys, double-buffered. bf16 hi/lo 3-product for QK^T and PV.
#define FSTR 144
#define FQ_BYTES (128*FSTR)       // 18432
#define FKV_MAT (64*FSTR)         // 9216
#define FSTAGE (4*FKV_MAT)        // 36864
#define FSMEM (2*FQ_BYTES + 2*FSTAGE)  // 110592

__global__ void __launch_bounds__(256, 2) k_fattn(
    const __nv_bfloat16* __restrict__ qh, const __nv_bfloat16* __restrict__ ql,
    __nv_bfloat16* __restrict__ yh, __nv_bfloat16* __restrict__ yl) {
    extern __shared__ char smem[];
    uint32_t sb = smem_u32(smem);
    uint32_t sQh = sb, sQl = sb + FQ_BYTES, sKV = sb + 2 * FQ_BYTES;
    int tid = threadIdx.x, lane = tid & 31, warp = tid >> 5;
    int q0 = blockIdx.x * 128, h = blockIdx.y, b = blockIdx.z;
    int rowbase = q0 + warp * 16;

    // Q load (once): 2048 x 16B
    for (int i = tid; i < 2048; i += 256) {
        int mat = i >> 10, rem = i & 1023, row = rem >> 3, seg = rem & 7;
        const __nv_bfloat16* src = (mat ? ql : qh)
            + (size_t)(b * Tz + q0 + row) * (3 * Cz) + h * 64 + seg * 8;
        cpasync16((mat ? sQl : sQh) + row * FSTR + seg * 16, src);
    }
    CP_COMMIT();

    auto load_kv = [&](int stage, int t0r) {
        uint32_t so = sKV + stage * FSTAGE;
        for (int i = tid; i < 2048; i += 256) {
            int mat = i >> 9, rem = i & 511, row = rem >> 3, seg = rem & 7;
            size_t g = (size_t)(b * Tz + t0r * 64 + row) * (3 * Cz) + h * 64 + seg * 8;
            const __nv_bfloat16* src =
                (mat == 0) ? qh + g + Cz :
                (mat == 1) ? ql + g + Cz :
                (mat == 2) ? qh + g + 2 * Cz : ql + g + 2 * Cz;
            cpasync16(so + mat * FKV_MAT + row * FSTR + seg * 16, src);
        }
        CP_COMMIT();
    };

    int ntiles = 2 * blockIdx.x + 2;
    load_kv(0, 0);
    load_kv(1, 1);

    float m0 = -1e30f, m1 = -1e30f, l0 = 0.f, l1 = 0.f;
    float O[8][4];
    #pragma unroll
    for (int j = 0; j < 8; j++)
        #pragma unroll
        for (int e = 0; e < 4; e++) O[j][e] = 0.f;

    int lrow = lane & 15;
    int lkb  = (lane >> 4) * 16;
    int r    = lane >> 2;
    int cc   = (lane & 3) * 2;

    for (int t = 0; t < ntiles; t++) {
        if (t + 1 < ntiles) asm volatile("cp.async.wait_group 1;\n" ::: "memory");
        else                asm volatile("cp.async.wait_group 0;\n" ::: "memory");
        __syncthreads();

        int t0 = t * 64;
        if (t0 <= rowbase + 15) {
            uint32_t so = sKV + (t & 1) * FSTAGE;
            float sc[8][4];
            #pragma unroll
            for (int j = 0; j < 8; j++)
                #pragma unroll
                for (int e = 0; e < 4; e++) sc[j][e] = 0.f;

            // scores = Q K^T (3-product)
            #pragma unroll
            for (int ks = 0; ks < 4; ks++) {
                uint32_t kb = (uint32_t)(ks * 32) + lkb;
                uint32_t aq[4], aql[4];
                ldm_x4(aq,  sQh + (warp * 16 + lrow) * FSTR + kb);
                ldm_x4(aql, sQl + (warp * 16 + lrow) * FSTR + kb);
                #pragma unroll
                for (int np = 0; np < 4; np++) {
                    uint32_t bk[4], bkl[4];
                    ldm_x4(bk,  so + (np * 16 + lrow) * FSTR + kb);
                    ldm_x4(bkl, so + FKV_MAT + (np * 16 + lrow) * FSTR + kb);
                    #pragma unroll
                    for (int hh = 0; hh < 2; hh++) {
                        int nt = np * 2 + hh;
                        mma16816(sc[nt], aq,  bk[hh],  bk[hh + 2]);
                        mma16816(sc[nt], aql, bk[hh],  bk[hh + 2]);
                        mma16816(sc[nt], aq,  bkl[hh], bkl[hh + 2]);
                    }
                }
            }

            // scale + causal mask
            bool needmask = (t0 + 63 > rowbase);
            #pragma unroll
            for (int nt = 0; nt < 8; nt++)
                #pragma unroll
                for (int e = 0; e < 4; e++) sc[nt][e] *= 0.125f;
            if (needmask) {
                #pragma unroll
                for (int nt = 0; nt < 8; nt++)
                    #pragma unroll
                    for (int e = 0; e < 4; e++) {
                        int col = t0 + nt * 8 + cc + (e & 1);
                        int rw  = rowbase + r + (e >> 1) * 8;
                        if (col > rw) sc[nt][e] = -1e30f;
                    }
            }

            // online softmax
            float tmax0 = -1e30f, tmax1 = -1e30f;
            #pragma unroll
            for (int nt = 0; nt < 8; nt++) {
                tmax0 = fmaxf(tmax0, fmaxf(sc[nt][0], sc[nt][1]));
                tmax1 = fmaxf(tmax1, fmaxf(sc[nt][2], sc[nt][3]));
            }
            tmax0 = fmaxf(tmax0, __shfl_xor_sync(0xffffffffu, tmax0, 1));
            tmax0 = fmaxf(tmax0, __shfl_xor_sync(0xffffffffu, tmax0, 2));
            tmax1 = fmaxf(tmax1, __shfl_xor_sync(0xffffffffu, tmax1, 1));
            tmax1 = fmaxf(tmax1, __shfl_xor_sync(0xffffffffu, tmax1, 2));
            float mn0 = fmaxf(m0, tmax0), mn1 = fmaxf(m1, tmax1);
            float scl0 = __expf(m0 - mn0), scl1 = __expf(m1 - mn1);
            float sum0 = 0.f, sum1 = 0.f;
            #pragma unroll
            for (int nt = 0; nt < 8; nt++) {
                sc[nt][0] = __expf(sc[nt][0] - mn0); sum0 += sc[nt][0];
                sc[nt][1] = __expf(sc[nt][1] - mn0); sum0 += sc[nt][1];
                sc[nt][2] = __expf(sc[nt][2] - mn1); sum1 += sc[nt][2];
                sc[nt][3] = __expf(sc[nt][3] - mn1); sum1 += sc[nt][3];
            }
            sum0 += __shfl_xor_sync(0xffffffffu, sum0, 1);
            sum0 += __shfl_xor_sync(0xffffffffu, sum0, 2);
            sum1 += __shfl_xor_sync(0xffffffffu, sum1, 1);
            sum1 += __shfl_xor_sync(0xffffffffu, sum1, 2);
            l0 = l0 * scl0 + sum0;
            l1 = l1 * scl1 + sum1;
            m0 = mn0; m1 = mn1;
            #pragma unroll
            for (int nt = 0; nt < 8; nt++) {
                O[nt][0] *= scl0; O[nt][1] *= scl0;
                O[nt][2] *= scl1; O[nt][3] *= scl1;
            }

            // PV (3-product), V^T via ldmatrix.trans
            #pragma unroll
            for (int kt = 0; kt < 4; kt++) {
                uint32_t ph[4], pl[4];
                ph[0] = pack_hi2(sc[2*kt][0],   sc[2*kt][1]);
                pl[0] = pack_lo2(sc[2*kt][0],   sc[2*kt][1]);
                ph[1] = pack_hi2(sc[2*kt][2],   sc[2*kt][3]);
                pl[1] = pack_lo2(sc[2*kt][2],   sc[2*kt][3]);
                ph[2] = pack_hi2(sc[2*kt+1][0], sc[2*kt+1][1]);
                pl[2] = pack_lo2(sc[2*kt+1][0], sc[2*kt+1][1]);
                ph[3] = pack_hi2(sc[2*kt+1][2], sc[2*kt+1][3]);
                pl[3] = pack_lo2(sc[2*kt+1][2], sc[2*kt+1][3]);
                #pragma unroll
                for (int db = 0; db < 4; db++) {
                    uint32_t vh[4], vl[4];
                    uint32_t va = so + (kt * 16 + lrow) * FSTR + db * 32 + lkb;
                    ldm_x4t(vh, va + 2 * FKV_MAT);
                    ldm_x4t(vl, va + 3 * FKV_MAT);
                    mma16816(O[2*db],     ph, vh[0], vh[1]);
                    mma16816(O[2*db],     pl, vh[0], vh[1]);
                    mma16816(O[2*db],     ph, vl[0], vl[1]);
                    mma16816(O[2*db + 1], ph, vh[2], vh[3]);
                    mma16816(O[2*db + 1], pl, vh[2], vh[3]);
                    mma16816(O[2*db + 1], ph, vl[2], vl[3]);
                }
            }
        }
        __syncthreads();
        if (t + 2 < ntiles) load_kv(t & 1, t + 2);
    }

    // epilogue: y = O / l  -> bf16 hi/lo
    float inv0 = 1.0f / l0, inv1 = 1.0f / l1;
    int ma = rowbase + r, mb = rowbase + 8 + r;
    #pragma unroll
    for (int nt = 0; nt < 8; nt++) {
        int col = nt * 8 + cc;
        size_t ga = (size_t)(b * Tz + ma) * Cz + h * 64 + col;
        size_t gb = (size_t)(b * Tz + mb) * Cz + h * 64 + col;
        float v0 = O[nt][0] * inv0, v1 = O[nt][1] * inv0;
        float v2 = O[nt][2] * inv1, v3 = O[nt][3] * inv1;
        __nv_bfloat16 h0, l0b, h1, l1b;
        split_bf16(v0, h0, l0b); split_bf16(v1, h1, l1b);
        *(__nv_bfloat162*)(yh + ga) = __nv_bfloat162(h0, h1);
        *(__nv_bfloat162*)(yl + ga) = __nv_bfloat162(l0b, l1b);
        split_bf16(v2, h0, l0b); split_bf16(v3, h1, l1b);
        *(__nv_bfloat162*)(yh + gb) = __nv_bfloat162(h0, h1);
        *(__nv_bfloat162*)(yl + gb) = __nv_bfloat162(l0b, l1b);
    }
}

// ---------------- driver ----------------------------------------------------
extern "C" void kernel_launch(void* const* d_in, const int* in_sizes, int n_in,
                              void* d_out, int out_size) {
    const int*   idx    = (const int*)  d_in[0];
    const float* wte    = (const float*)d_in[1];
    const float* wpe    = (const float*)d_in[2];
    const float* ln1_w  = (const float*)d_in[3];
    const float* ln1_b  = (const float*)d_in[4];
    const float* attn_w = (const float*)d_in[5];
    const float* attn_b = (const float*)d_in[6];
    const float* proj_w = (const float*)d_in[7];
    const float* proj_b = (const float*)d_in[8];
    const float* ln2_w  = (const float*)d_in[9];
    const float* ln2_b  = (const float*)d_in[10];
    const float* fc_w   = (const float*)d_in[11];
    const float* fc_b   = (const float*)d_in[12];
    const float* mlp_w  = (const float*)d_in[13];
    const float* mlp_b  = (const float*)d_in[14];
    const float* lnf_w  = (const float*)d_in[15];
    const float* lnf_b  = (const float*)d_in[16];
    const float* head_w = (const float*)d_in[17];
    float* out = (float*)d_out;

    float *px, *pwht, *plnt;
    __nv_bfloat16 *plnh, *plnl, *pyh, *pyl, *phh, *phl, *pqh, *pql;
    __nv_bfloat16 *wqh, *wql, *wph, *wpl, *wfh, *wfl, *wmh, *wml;
    cudaGetSymbolAddress((void**)&px,   g_x);
    cudaGetSymbolAddress((void**)&pqh,  g_qkvh);
    cudaGetSymbolAddress((void**)&pql,  g_qkvl);
    cudaGetSymbolAddress((void**)&plnh, g_lnh);
    cudaGetSymbolAddress((void**)&plnl, g_lnl);
    cudaGetSymbolAddress((void**)&pyh,  g_yh);
    cudaGetSymbolAddress((void**)&pyl,  g_yl);
    cudaGetSymbolAddress((void**)&phh,  g_hh);
    cudaGetSymbolAddress((void**)&phl,  g_hl);
    cudaGetSymbolAddress((void**)&wqh,  g_wqkv_h);
    cudaGetSymbolAddress((void**)&wql,  g_wqkv_l);
    cudaGetSymbolAddress((void**)&wph,  g_wproj_h);
    cudaGetSymbolAddress((void**)&wpl,  g_wproj_l);
    cudaGetSymbolAddress((void**)&wfh,  g_wfc_h);
    cudaGetSymbolAddress((void**)&wfl,  g_wfc_l);
    cudaGetSymbolAddress((void**)&wmh,  g_wmlp_h);
    cudaGetSymbolAddress((void**)&wml,  g_wmlp_l);
    cudaGetSymbolAddress((void**)&pwht, g_whead_t);
    cudaGetSymbolAddress((void**)&plnt, g_lnt);

    cudaFuncSetAttribute(k_mgemm, cudaFuncAttributeMaxDynamicSharedMemorySize, MG_SMEM);
    cudaFuncSetAttribute(k_tgemm, cudaFuncAttributeMaxDynamicSharedMemorySize, TG_SMEM);
    cudaFuncSetAttribute(k_fattn, cudaFuncAttributeMaxDynamicSharedMemorySize, FSMEM);

    dim3 tp(32, 8);
    // ---- launches 1-3 so my launch #4 (= ncu capture slot) is k_fattn ----
    k_wprep<<<dim3(3*Cz/32, Cz/32), tp>>>(attn_w, wqh, wql, Cz, 3*Cz);     // 1
    k_embed_ln<<<BT, 256>>>(idx, wte, wpe, ln1_w, ln1_b, plnh, plnl);      // 2
    k_mgemm<<<dim3(3*Cz/128, BT/64), 256, MG_SMEM>>>(                      // 3
        plnh, plnl, wqh, wql, attn_b, nullptr, nullptr, pqh, pql,
        BT, 3*Cz, Cz, 4);
    k_fattn<<<dim3(Tz/128, Hz, Bz), 256, FSMEM>>>(pqh, pql, pyh, pyl);     // 4 (ncu)

    // remaining weight preps
    k_wprep<<<dim3(Cz/32, Cz/32), tp>>>(proj_w, wph, wpl, Cz, Cz);
    k_wprep<<<dim3(4*Cz/32, Cz/32), tp>>>(fc_w, wfh, wfl, Cz, 4*Cz);
    k_wprep<<<dim3(Cz/32, 4*Cz/32), tp>>>(mlp_w, wmh, wml, 4*Cz, Cz);
    for (int l = 1; l < Lz; l++) {
        k_wprep<<<dim3(3*Cz/32, Cz/32), tp>>>(attn_w + (size_t)l*Cz*3*Cz,
            wqh + (size_t)l*3*Cz*Cz, wql + (size_t)l*3*Cz*Cz, Cz, 3*Cz);
        k_wprep<<<dim3(Cz/32, Cz/32), tp>>>(proj_w + (size_t)l*Cz*Cz,
            wph + (size_t)l*Cz*Cz, wpl + (size_t)l*Cz*Cz, Cz, Cz);
        k_wprep<<<dim3(4*Cz/32, Cz/32), tp>>>(fc_w + (size_t)l*Cz*4*Cz,
            wfh + (size_t)l*4*Cz*Cz, wfl + (size_t)l*4*Cz*Cz, Cz, 4*Cz);
        k_wprep<<<dim3(Cz/32, 4*Cz/32), tp>>>(mlp_w + (size_t)l*4*Cz*Cz,
            wmh + (size_t)l*Cz*4*Cz, wml + (size_t)l*Cz*4*Cz, 4*Cz, Cz);
    }
    k_wprep_head<<<dim3(Vz/32, Cz/32), tp>>>(head_w, pwht);

    for (int l = 0; l < Lz; l++) {
        const float* ab = attn_b + (size_t)l * 3 * Cz;
        const float* pb = proj_b + (size_t)l * Cz;
        const float* fb = fc_b   + (size_t)l * 4 * Cz;
        const float* mb = mlp_b  + (size_t)l * Cz;

        if (l > 0) {
            k_ln<<<BT, 256>>>(px, ln1_w + (size_t)l*Cz, ln1_b + (size_t)l*Cz, plnh, plnl);
            k_mgemm<<<dim3(3*Cz/128, BT/64), 256, MG_SMEM>>>(
                plnh, plnl, wqh + (size_t)l*3*Cz*Cz, wql + (size_t)l*3*Cz*Cz,
                ab, nullptr, nullptr, pqh, pql, BT, 3*Cz, Cz, 4);
            k_fattn<<<dim3(Tz/128, Hz, Bz), 256, FSMEM>>>(pqh, pql, pyh, pyl);
        }
        // x += y @ Wproj + b       [4096, 768]
        k_mgemm<<<dim3(Cz/128, BT/64), 256, MG_SMEM>>>(
            pyh, pyl, wph + (size_t)l*Cz*Cz, wpl + (size_t)l*Cz*Cz,
            pb, px, px, nullptr, nullptr, BT, Cz, Cz, 1);
        k_ln<<<BT, 256>>>(px, ln2_w + (size_t)l*Cz, ln2_b + (size_t)l*Cz, plnh, plnl);
        // h = gelu(ln2 @ Wfc + b)  [4096, 3072]
        k_mgemm<<<dim3(4*Cz/128, BT/64), 256, MG_SMEM>>>(
            plnh, plnl, wfh + (size_t)l*4*Cz*Cz, wfl + (size_t)l*4*Cz*Cz,
            fb, nullptr, nullptr, phh, phl, BT, 4*Cz, Cz, 2);
        // x += h @ Wmlp + b        [4096, 768], K=3072
        k_mgemm<<<dim3(Cz/128, BT/64), 256, MG_SMEM>>>(
            phh, phl, wmh + (size_t)l*Cz*4*Cz, wml + (size_t)l*Cz*4*Cz,
            mb, px, px, nullptr, nullptr, BT, Cz, 4*Cz, 1);
    }

    // final layernorm -> A-perm tf32, then tf32 head GEMM
    k_lnp<<<BT, 256>>>(px, lnf_w, lnf_b, plnt);
    k_tgemm<<<dim3(Vz/128, BT/64), 256, TG_SMEM>>>(plnt, pwht, out, BT, Vz, Cz);
}